// round 13
// baseline (speedup 1.0000x reference)
#include <cuda_runtime.h>
#include <cuda_bf16.h>
#include <math.h>
#include <stdint.h>

// ---------------------------------------------------------------------------
// Problem constants
// ---------------------------------------------------------------------------
#define BSZ   4
#define LEN   2048
#define DIM   1024
#define NH    8
#define NE    16
#define TOPK  2
#define HD    128
#define II    512
#define NTOK  (BSZ*LEN)    // 8192
#define NSUB  (NTOK*NH)    // 65536
#define NPAIR (NSUB*TOPK)  // 131072
#define MAXTILES (NPAIR/128 + NE)   // 1040

// ---------------------------------------------------------------------------
// Device scratch
// ---------------------------------------------------------------------------
__device__ float    g_h   [(size_t)NTOK * DIM];
__device__ float    g_comb[(size_t)NTOK * DIM];
__device__ uint32_t g_hH  [(size_t)NSUB * HD / 2];
__device__ uint32_t g_hL  [(size_t)NSUB * HD / 2];
__device__ uint32_t g_mH  [(size_t)NPAIR * II / 2];
__device__ uint32_t g_mL  [(size_t)NPAIR * II / 2];
__device__ int   g_topi[NPAIR];
__device__ float g_topw[NPAIR];
__device__ int   g_perm[NPAIR];
__device__ float g_wslot[NPAIR];
__device__ int   g_counts[NE];
__device__ int   g_cursor[NE];
__device__ int   g_offsets[NE + 1];
__device__ int2  g_tilemap[MAXTILES];
__device__ int   g_ntiles;

// Prepacked weights: hi/lo bf16x2 (packed along k), transposed to [N][K/2]
__device__ uint32_t g_WmH[(size_t)DIM * DIM / 2];
__device__ uint32_t g_WmL[(size_t)DIM * DIM / 2];
__device__ uint32_t g_W1H[(size_t)NE * II * HD / 2];
__device__ uint32_t g_W1L[(size_t)NE * II * HD / 2];
__device__ uint32_t g_W2H[(size_t)NE * HD * II / 2];
__device__ uint32_t g_W2L[(size_t)NE * HD * II / 2];
__device__ uint32_t g_WoH[(size_t)DIM * DIM / 2];
__device__ uint32_t g_WoL[(size_t)DIM * DIM / 2];

__device__ __forceinline__ float gelu_exact(float x) {
    return 0.5f * x * (1.0f + erff(x * 0.70710678118654752440f));
}
__device__ __forceinline__ uint32_t pack_bf16x2(float e0, float e1) {
    uint32_t r;
    asm("cvt.rn.bf16x2.f32 %0, %1, %2;" : "=r"(r) : "f"(e1), "f"(e0));
    return r;
}
__device__ __forceinline__ float bf16_rt(float x) {
    return __bfloat162float(__float2bfloat16(x));
}
__device__ __forceinline__ void mma_bf16(float* d, const uint32_t* a, const uint32_t* b) {
    asm volatile(
        "mma.sync.aligned.m16n8k16.row.col.f32.bf16.bf16.f32 "
        "{%0,%1,%2,%3}, {%4,%5,%6,%7}, {%8,%9}, {%0,%1,%2,%3};\n"
        : "+f"(d[0]), "+f"(d[1]), "+f"(d[2]), "+f"(d[3])
        : "r"(a[0]), "r"(a[1]), "r"(a[2]), "r"(a[3]), "r"(b[0]), "r"(b[1]));
}
__device__ __forceinline__ void ldsm_x4(uint32_t& r0, uint32_t& r1,
                                        uint32_t& r2, uint32_t& r3, uint32_t addr) {
    asm volatile("ldmatrix.sync.aligned.m8n8.x4.shared.b16 {%0,%1,%2,%3}, [%4];"
                 : "=r"(r0), "=r"(r1), "=r"(r2), "=r"(r3) : "r"(addr));
}
__device__ __forceinline__ uint32_t smem_u32(const void* p) {
    return (uint32_t)__cvta_generic_to_shared(p);
}

#define CP16(dst, src) \
    asm volatile("cp.async.cg.shared.global [%0], [%1], 16;" :: "r"(dst), "l"(src))
#define CP16Z(dst, src, sz) \
    asm volatile("cp.async.cg.shared.global [%0], [%1], 16, %2;" :: "r"(dst), "l"(src), "r"(sz))

// ---------------------------------------------------------------------------
// Weight prepack: B[K][N] (row-major, per expert) -> hi/lo [N][K/2] uint32
// ---------------------------------------------------------------------------
__global__ void prepack_kernel(const float* __restrict__ B,
                               uint32_t* __restrict__ Hi, uint32_t* __restrict__ Lo,
                               int K, int N)
{
    const int e = blockIdx.z;
    B  += (size_t)e * K * N;
    Hi += (size_t)e * N * (K / 2);
    Lo += (size_t)e * N * (K / 2);

    __shared__ float tile[64][33];
    const int tid = threadIdx.x;
    const int k0 = blockIdx.y * 64;
    const int n0 = blockIdx.x * 32;

#pragma unroll
    for (int i = 0; i < 8; i++) {
        const int row = i * 8 + (tid >> 5);
        const int col = tid & 31;
        tile[row][col] = B[(size_t)(k0 + row) * N + n0 + col];
    }
    __syncthreads();

#pragma unroll
    for (int j = 0; j < 4; j++) {
        const int nl = (tid >> 5) * 4 + j;
        const int kp = tid & 31;
        const float x0 = tile[2 * kp][nl];
        const float x1 = tile[2 * kp + 1][nl];
        const float h0 = bf16_rt(x0), h1 = bf16_rt(x1);
        const size_t o = (size_t)(n0 + nl) * (K / 2) + k0 / 2 + kp;
        Hi[o] = pack_bf16x2(h0, h1);
        Lo[o] = pack_bf16x2(x0 - h0, x1 - h1);
    }
}

__global__ void zero_comb() {
    int i = blockIdx.x * blockDim.x + threadIdx.x;
    reinterpret_cast<float4*>(g_comb)[i] = make_float4(0.f, 0.f, 0.f, 0.f);
}

// ---------------------------------------------------------------------------
// bf16-split tensor GEMM.
//  APACKED: A supplied as prepacked hi/lo bf16x2 [rows][K/2]; pure cp.async
//           staging (A 2-stage, B 3-stage, one barrier per tile).
//  else:    A fp32; R12 path (reg prefetch + convert; A 2-stage, B 3-stage).
//  OUT_PAIR:   epilogue emits hi/lo bf16x2 pairs (for hmid).
//  OUT_ATOMIC: epilogue does w-scaled atomic combine into Cout[NSUB][N].
// ---------------------------------------------------------------------------
#define TSTRIDE 20
#define TILE_B  (128 * TSTRIDE * 4)       // 10240 bytes
#define SMEM_BYTES (10 * TILE_B)          // 102400

template<bool APACKED, bool GROUPED, bool GATHER, bool DO_GELU, bool OUT_PAIR, bool OUT_ATOMIC>
__global__ __launch_bounds__(256, 2)
void mma_gemm(const float* __restrict__ Af,
              const uint32_t* __restrict__ AH, const uint32_t* __restrict__ AL,
              const uint32_t* __restrict__ BpH, const uint32_t* __restrict__ BpL,
              const float* __restrict__ biasAll,
              float* __restrict__ CoutF,
              uint32_t* __restrict__ CoutH, uint32_t* __restrict__ CoutL,
              int M, int N, int K)
{
    extern __shared__ __align__(16) uint32_t smem[];

    int rows = M, segBase = 0, m0, n0;
    const float* bias;
    if (GROUPED) {
        if ((int)blockIdx.x >= g_ntiles) return;
        const int2 tm = g_tilemap[blockIdx.x];
        const int e = tm.x;
        m0      = tm.y;
        rows    = g_counts[e];
        segBase = g_offsets[e];
        n0      = blockIdx.y * 128;
        BpH    += (size_t)e * N * (K / 2);
        BpL    += (size_t)e * N * (K / 2);
        bias    = biasAll + (size_t)e * N;
    } else {
        m0   = blockIdx.y * 128;
        n0   = blockIdx.x * 128;
        bias = biasAll;
    }

    const int tid  = threadIdx.x;
    const int lane = tid & 31;
    const int wid  = tid >> 5;
    const int g    = lane >> 2;
    const int tig  = lane & 3;
    const int wm   = (wid & 1) * 64;
    const int wn   = (wid >> 1) * 32;

    const uint32_t base = smem_u32(smem);
    const int Kp = K / 2;

    // ---- fp32-A path state ----
    const int acol = (tid & 7) * 4;
    const float* arow[4];
    bool aval[4];
    // ---- packed-A path state ----
    const uint32_t* aPH = nullptr;
    const uint32_t* aPL = nullptr;
    uint32_t aSz = 16, a_stp = 0;

    if (APACKED) {
        const int srow = tid >> 1;
        const int half = tid & 1;
        int gr = m0 + srow, row = 0;
        if (GROUPED) {
            if (gr < rows) row = GATHER ? g_perm[segBase + gr] : (segBase + gr);
            else           aSz = 0;
        } else row = gr;
        aPH = AH + (size_t)row * Kp + half * 8;
        aPL = AL + (size_t)row * Kp + half * 8;
        a_stp = (srow * TSTRIDE + half * 8) * 4;
    } else {
#pragma unroll
        for (int v = 0; v < 4; v++) {
            const int r  = v * 32 + (tid >> 3);
            const int gr = m0 + r;
            if (GROUPED) {
                aval[v] = (gr < rows);
                int row = 0;
                if (aval[v]) row = GATHER ? g_perm[segBase + gr] : (segBase + gr);
                arow[v] = Af + (size_t)row * K + acol;
            } else {
                aval[v] = true;
                arow[v] = Af + (size_t)gr * K + acol;
            }
        }
    }
    const uint32_t a_st = (((tid >> 3) * TSTRIDE) + (acol >> 1)) * 4;

    // B staging
    const int bcol  = tid >> 1;
    const int bkp   = (tid & 1) * 8;
    const uint32_t* bptrH = BpH + (size_t)(n0 + bcol) * Kp + bkp;
    const uint32_t* bptrL = BpL + (size_t)(n0 + bcol) * Kp + bkp;
    const uint32_t b_st = (bcol * TSTRIDE + bkp) * 4;

    // ldmatrix per-lane addresses (stage-local byte offsets)
    const uint32_t a_off = (((wm + (lane & 15)) * TSTRIDE) + ((lane >> 4) * 4)) * 4;
    const uint32_t b_off = (((wn + ((lane >> 4) & 1) * 8 + (lane & 7)) * TSTRIDE)
                            + (((lane >> 3) & 1) * 4)) * 4;

    float acc[4][4][4];
#pragma unroll
    for (int m = 0; m < 4; m++)
#pragma unroll
        for (int n = 0; n < 4; n++)
#pragma unroll
            for (int i = 0; i < 4; i++) acc[m][n][i] = 0.0f;

    const int KT = K / 32;

    auto issue_B = [&](int kt, int j) {
        const int kpo = kt * 16;
        const uint32_t dB = base + (4 + 2 * j) * TILE_B + b_st;
        CP16(dB,               bptrH + kpo);
        CP16(dB + 16,          bptrH + kpo + 4);
        CP16(dB + TILE_B,      bptrL + kpo);
        CP16(dB + TILE_B + 16, bptrL + kpo + 4);
        asm volatile("cp.async.commit_group;");
    };
    auto issue_A = [&](int kt, int sa) {   // packed-A only
        const int kpo = kt * 16;
        const uint32_t dA = base + sa * 2 * TILE_B + a_stp;
        CP16Z(dA,               aPH + kpo,     aSz);
        CP16Z(dA + 16,          aPH + kpo + 4, aSz);
        CP16Z(dA + TILE_B,      aPL + kpo,     aSz);
        CP16Z(dA + TILE_B + 16, aPL + kpo + 4, aSz);
        asm volatile("cp.async.commit_group;");
    };
    float4 areg[4];
    auto convert_A = [&](int sa) {         // fp32-A only
        const uint32_t sbase = base + sa * 2 * TILE_B;
#pragma unroll
        for (int v = 0; v < 4; v++) {
            const float hx = bf16_rt(areg[v].x), hy = bf16_rt(areg[v].y);
            const float hz = bf16_rt(areg[v].z), hw = bf16_rt(areg[v].w);
            uint2 hv, lv;
            hv.x = pack_bf16x2(hx, hy);
            hv.y = pack_bf16x2(hz, hw);
            lv.x = pack_bf16x2(areg[v].x - hx, areg[v].y - hy);
            lv.y = pack_bf16x2(areg[v].z - hz, areg[v].w - hw);
            const uint32_t d = sbase + a_st + v * 32 * TSTRIDE * 4;
            asm volatile("st.shared.v2.b32 [%0], {%1,%2};" :: "r"(d), "r"(hv.x), "r"(hv.y));
            asm volatile("st.shared.v2.b32 [%0], {%1,%2};"
                         :: "r"(d + TILE_B), "r"(lv.x), "r"(lv.y));
        }
    };
    auto fetch_A = [&](int kt) {           // fp32-A only
        const int ko = kt * 32;
#pragma unroll
        for (int v = 0; v < 4; v++) {
            areg[v] = make_float4(0.f, 0.f, 0.f, 0.f);
            if (aval[v]) areg[v] = *reinterpret_cast<const float4*>(arow[v] + ko);
        }
    };

    // ---- preloop ----
    if (APACKED) {
        // group order: B0, A0, B1
        issue_B(0, 0);
        issue_A(0, 0);
        if (KT > 1) issue_B(1, 1);
    } else {
        fetch_A(0);
        convert_A(0);
        issue_B(0, 0);
        if (KT > 1) { fetch_A(1); issue_B(1, 1); }
    }

    for (int kt = 0; kt < KT; kt++) {
        const int sA = kt & 1;
        const int sB = kt % 3;

        if (APACKED) {
            // pending (steady): B(kt), A(kt), B(kt+1) -> need first two done
            if (kt + 1 < KT) asm volatile("cp.async.wait_group 1;" ::: "memory");
            else             asm volatile("cp.async.wait_group 0;" ::: "memory");
            __syncthreads();
            if (kt + 1 < KT) issue_A(kt + 1, (kt + 1) & 1);
            if (kt + 2 < KT) issue_B(kt + 2, (kt + 2) % 3);
        } else {
            if (kt + 1 < KT) asm volatile("cp.async.wait_group 1;" ::: "memory");
            else             asm volatile("cp.async.wait_group 0;" ::: "memory");
            __syncthreads();
            if (kt + 2 < KT) issue_B(kt + 2, (kt + 2) % 3);
        }

        const uint32_t aH_addr = base + sA * 2 * TILE_B + a_off;
        const uint32_t aL_addr = aH_addr + TILE_B;
        const uint32_t bH_addr = base + (4 + 2 * sB) * TILE_B + b_off;
        const uint32_t bL_addr = bH_addr + TILE_B;

#pragma unroll
        for (int ks = 0; ks < 2; ks++) {
            const uint32_t ksb = ks * 32;
            uint32_t bH[4][2], bL[4][2];
            ldsm_x4(bH[0][0], bH[0][1], bH[1][0], bH[1][1], bH_addr + ksb);
            ldsm_x4(bH[2][0], bH[2][1], bH[3][0], bH[3][1], bH_addr + ksb + 16 * TSTRIDE * 4);
            ldsm_x4(bL[0][0], bL[0][1], bL[1][0], bL[1][1], bL_addr + ksb);
            ldsm_x4(bL[2][0], bL[2][1], bL[3][0], bL[3][1], bL_addr + ksb + 16 * TSTRIDE * 4);
#pragma unroll
            for (int m = 0; m < 4; m++) {
                const uint32_t mb = m * 16 * TSTRIDE * 4;
                uint32_t aH[4], aL[4];
                ldsm_x4(aH[0], aH[1], aH[2], aH[3], aH_addr + mb + ksb);
                ldsm_x4(aL[0], aL[1], aL[2], aL[3], aL_addr + mb + ksb);
#pragma unroll
                for (int n = 0; n < 4; n++) {
                    mma_bf16(acc[m][n], aH, bH[n]);
                    mma_bf16(acc[m][n], aH, bL[n]);
                    mma_bf16(acc[m][n], aL, bH[n]);
                }
            }
        }

        if (!APACKED && kt + 1 < KT) {
            convert_A((kt + 1) & 1);
            if (kt + 2 < KT) fetch_A(kt + 2);
        }
    }

    // ---- epilogue ----
    if (OUT_ATOMIC) {
#pragma unroll
        for (int m = 0; m < 4; m++) {
            const int r0 = wm + m * 16 + g;
            int   tok[2]; float w[2]; bool ok[2];
#pragma unroll
            for (int h = 0; h < 2; h++) {
                const int gr = m0 + r0 + 8 * h;
                ok[h] = gr < rows;
                if (ok[h]) {
                    const int slot = segBase + gr;
                    tok[h] = g_perm[slot];
                    w[h]   = g_wslot[slot];
                } else { tok[h] = 0; w[h] = 0.f; }
            }
#pragma unroll
            for (int n = 0; n < 4; n++) {
                const int col = n0 + wn + n * 8 + 2 * tig;
                const float b0 = bias[col];
                const float b1 = bias[col + 1];
                if (ok[0]) {
                    float* p = CoutF + (size_t)tok[0] * N + col;
                    atomicAdd(p,     w[0] * (acc[m][n][0] + b0));
                    atomicAdd(p + 1, w[0] * (acc[m][n][1] + b1));
                }
                if (ok[1]) {
                    float* p = CoutF + (size_t)tok[1] * N + col;
                    atomicAdd(p,     w[1] * (acc[m][n][2] + b0));
                    atomicAdd(p + 1, w[1] * (acc[m][n][3] + b1));
                }
            }
        }
    } else {
#pragma unroll
        for (int n = 0; n < 4; n++) {
            const int col = n0 + wn + n * 8 + 2 * tig;
            const float b0 = bias[col];
            const float b1 = bias[col + 1];
#pragma unroll
            for (int m = 0; m < 4; m++) {
                const int r0 = wm + m * 16 + g;
                float v00 = acc[m][n][0] + b0;
                float v01 = acc[m][n][1] + b1;
                float v10 = acc[m][n][2] + b0;
                float v11 = acc[m][n][3] + b1;
                if (DO_GELU) {
                    v00 = gelu_exact(v00); v01 = gelu_exact(v01);
                    v10 = gelu_exact(v10); v11 = gelu_exact(v11);
                }
                const bool ok0 = !GROUPED || (m0 + r0 < rows);
                const bool ok1 = !GROUPED || (m0 + r0 + 8 < rows);
                const size_t gr0 = (size_t)(segBase + m0 + r0);
                const size_t gr1 = gr0 + 8;
                if (OUT_PAIR) {
                    const int ci = col >> 1;
                    if (ok0) {
                        float h0 = bf16_rt(v00), h1 = bf16_rt(v01);
                        CoutH[gr0 * (N / 2) + ci] = pack_bf16x2(h0, h1);
                        CoutL[gr0 * (N / 2) + ci] = pack_bf16x2(v00 - h0, v01 - h1);
                    }
                    if (ok1) {
                        float h0 = bf16_rt(v10), h1 = bf16_rt(v11);
                        CoutH[gr1 * (N / 2) + ci] = pack_bf16x2(h0, h1);
                        CoutL[gr1 * (N / 2) + ci] = pack_bf16x2(v10 - h0, v11 - h1);
                    }
                } else {
                    if (ok0)
                        *reinterpret_cast<float2*>(CoutF + gr0 * N + col) = make_float2(v00, v01);
                    if (ok1)
                        *reinterpret_cast<float2*>(CoutF + gr1 * N + col) = make_float2(v10, v11);
                }
            }
        }
    }
}

// ---------------------------------------------------------------------------
// Routing: one warp per sub-token + fused histogram + packed h emission.
// ---------------------------------------------------------------------------
__global__ void routing_kernel(const float* __restrict__ emb)
{
    __shared__ int loc[NE];
    if (threadIdx.x < NE) loc[threadIdx.x] = 0;
    __syncthreads();

    const int warp = (blockIdx.x * blockDim.x + threadIdx.x) >> 5;
    const int lane = threadIdx.x & 31;

    const float2* trow2 = reinterpret_cast<const float2*>(g_h + (size_t)warp * HD);
    const float2 p0 = trow2[lane];        // elems 2l, 2l+1
    const float2 p1 = trow2[lane + 32];   // elems 64+2l, 64+2l+1

    // emit packed hi/lo pairs (side effect; GEMM1 operand source)
    {
        uint32_t* hHp = g_hH + (size_t)warp * (HD / 2);
        uint32_t* hLp = g_hL + (size_t)warp * (HD / 2);
        float h0 = bf16_rt(p0.x), h1 = bf16_rt(p0.y);
        hHp[lane]      = pack_bf16x2(h0, h1);
        hLp[lane]      = pack_bf16x2(p0.x - h0, p0.y - h1);
        h0 = bf16_rt(p1.x); h1 = bf16_rt(p1.y);
        hHp[lane + 32] = pack_bf16x2(h0, h1);
        hLp[lane + 32] = pack_bf16x2(p1.x - h0, p1.y - h1);
    }

    const int k0 = 2 * lane, k1 = 2 * lane + 64;
    float logits[NE];
#pragma unroll
    for (int e = 0; e < NE; e++) {
        float p = p0.x * emb[(k0    ) * NE + e]
                + p0.y * emb[(k0 + 1) * NE + e]
                + p1.x * emb[(k1    ) * NE + e]
                + p1.y * emb[(k1 + 1) * NE + e];
#pragma unroll
        for (int s = 16; s > 0; s >>= 1) p += __shfl_xor_sync(0xffffffffu, p, s);
        logits[e] = p;
    }

    float mx = logits[0];
#pragma unroll
    for (int e = 1; e < NE; e++) mx = fmaxf(mx, logits[e]);
    float sum = 0.0f;
#pragma unroll
    for (int e = 0; e < NE; e++) { logits[e] = expf(logits[e] - mx); sum += logits[e]; }
    const float inv = 1.0f / sum;

    int i0 = 0; float v0 = logits[0];
#pragma unroll
    for (int e = 1; e < NE; e++) if (logits[e] > v0) { v0 = logits[e]; i0 = e; }
    int i1 = -1; float v1 = -1.0f;
#pragma unroll
    for (int e = 0; e < NE; e++) if (e != i0 && logits[e] > v1) { v1 = logits[e]; i1 = e; }

    if (lane == 0) {
        g_topi[2 * warp + 0] = i0;
        g_topi[2 * warp + 1] = i1;
        g_topw[2 * warp + 0] = v0 * inv;
        g_topw[2 * warp + 1] = v1 * inv;
        atomicAdd(&loc[i0], 1);
        atomicAdd(&loc[i1], 1);
    }
    __syncthreads();
    if (threadIdx.x < NE && loc[threadIdx.x])
        atomicAdd(&g_counts[threadIdx.x], loc[threadIdx.x]);
}

// ---------------------------------------------------------------------------
// Routing bookkeeping
// ---------------------------------------------------------------------------
__global__ void zero_counts() {
    int i = threadIdx.x;
    if (i < NE) { g_counts[i] = 0; g_cursor[i] = 0; }
}
__global__ void scan_kernel() {
    int s = 0;
    for (int e = 0; e < NE; e++) { g_offsets[e] = s; s += g_counts[e]; }
    g_offsets[NE] = s;
}
__global__ void build_tiles() {
    const int e = threadIdx.x;
    if (e >= NE) return;
    int start = 0;
#pragma unroll
    for (int j = 0; j < NE; j++) {
        int tj = (g_counts[j] + 127) >> 7;
        if (j < e) start += tj;
        if (e == NE - 1 && j == NE - 1) g_ntiles = start + tj;
    }
    const int nt = (g_counts[e] + 127) >> 7;
    for (int t = 0; t < nt; t++)
        g_tilemap[start + t] = make_int2(e, t << 7);
}
__global__ void scatter_kernel() {
    __shared__ int bcnt[NE];
    __shared__ int bbase[NE];
    if (threadIdx.x < NE) bcnt[threadIdx.x] = 0;
    __syncthreads();

    const int i    = blockIdx.x * blockDim.x + threadIdx.x;
    const int lane = threadIdx.x & 31;
    const int e    = g_topi[i];

    unsigned mask    = __match_any_sync(0xffffffffu, e);
    const int leader = __ffs(mask) - 1;
    const int lrank  = __popc(mask & ((1u << lane) - 1));
    int wbase = 0;
    if (lane == leader) wbase = atomicAdd(&bcnt[e], __popc(mask));
    wbase = __shfl_sync(0xffffffffu, wbase, leader);
    __syncthreads();

    if (threadIdx.x < NE)
        bbase[threadIdx.x] = bcnt[threadIdx.x]
            ? atomicAdd(&g_cursor[threadIdx.x], bcnt[threadIdx.x]) : 0;
    __syncthreads();

    const int slot = g_offsets[e] + bbase[e] + wbase + lrank;
    g_perm[slot]  = i >> 1;
    g_wslot[slot] = g_topw[i];
}

// ---------------------------------------------------------------------------
// Launch
// ---------------------------------------------------------------------------
extern "C" void kernel_launch(void* const* d_in, const int* in_sizes, int n_in,
                              void* d_out, int out_size)
{
    (void)in_sizes; (void)n_in; (void)out_size;
    const float* x   = (const float*)d_in[0];
    const float* Wm  = (const float*)d_in[1];
    const float* bm  = (const float*)d_in[2];
    const float* emb = (const float*)d_in[3];
    const float* W1  = (const float*)d_in[4];
    const float* b1  = (const float*)d_in[5];
    const float* W2  = (const float*)d_in[6];
    const float* b2  = (const float*)d_in[7];
    const float* Wo  = (const float*)d_in[8];
    const float* bo  = (const float*)d_in[9];
    float* out = (float*)d_out;

    float *h_p, *comb_p;
    cudaGetSymbolAddress((void**)&h_p,    g_h);
    cudaGetSymbolAddress((void**)&comb_p, g_comb);
    uint32_t *hH,*hL,*mH,*mL;
    cudaGetSymbolAddress((void**)&hH, g_hH); cudaGetSymbolAddress((void**)&hL, g_hL);
    cudaGetSymbolAddress((void**)&mH, g_mH); cudaGetSymbolAddress((void**)&mL, g_mL);
    uint32_t *WmH, *WmL, *W1H, *W1L, *W2H, *W2L, *WoH, *WoL;
    cudaGetSymbolAddress((void**)&WmH, g_WmH); cudaGetSymbolAddress((void**)&WmL, g_WmL);
    cudaGetSymbolAddress((void**)&W1H, g_W1H); cudaGetSymbolAddress((void**)&W1L, g_W1L);
    cudaGetSymbolAddress((void**)&W2H, g_W2H); cudaGetSymbolAddress((void**)&W2L, g_W2L);
    cudaGetSymbolAddress((void**)&WoH, g_WoH); cudaGetSymbolAddress((void**)&WoL, g_WoL);

    cudaFuncSetAttribute(mma_gemm<false,false,false,false,false,false>,
                         cudaFuncAttributeMaxDynamicSharedMemorySize, SMEM_BYTES);
    cudaFuncSetAttribute(mma_gemm<true,true,true,true,true,false>,
                         cudaFuncAttributeMaxDynamicSharedMemorySize, SMEM_BYTES);
    cudaFuncSetAttribute(mma_gemm<true,true,false,false,false,true>,
                         cudaFuncAttributeMaxDynamicSharedMemorySize, SMEM_BYTES);

    // 0) prepack weights + zero combine accumulator + zero counts
    zero_comb<<<(NTOK * DIM / 4) / 256, 256>>>();
    zero_counts<<<1, 32>>>();
    prepack_kernel<<<dim3(DIM/32, DIM/64, 1),  256>>>(Wm, WmH, WmL, DIM, DIM);
    prepack_kernel<<<dim3(II/32,  HD/64,  NE), 256>>>(W1, W1H, W1L, HD, II);
    prepack_kernel<<<dim3(HD/32,  II/64,  NE), 256>>>(W2, W2H, W2L, II, HD);
    prepack_kernel<<<dim3(DIM/32, DIM/64, 1),  256>>>(Wo, WoH, WoL, DIM, DIM);

    // 1) h = x @ Wm + bm  (fp32 A path)
    mma_gemm<false,false,false,false,false,false>
        <<<dim3(DIM/128, NTOK/128), 256, SMEM_BYTES>>>(
        x, nullptr, nullptr, WmH, WmL, bm, h_p, nullptr, nullptr, NTOK, DIM, DIM);

    // 2) routing (+ fused histogram + packed h emission)
    routing_kernel<<<NSUB / 16, 512>>>(emb);

    // 3) expert bookkeeping + tile worklist
    scan_kernel<<<1, 1>>>();
    build_tiles<<<1, NE>>>();
    scatter_kernel<<<NPAIR / 256, 256>>>();

    // 4) hmid = gelu(t @ W1[e] + b1[e])  (packed gathered A -> packed out)
    mma_gemm<true,true,true,true,true,false>
        <<<dim3(MAXTILES, II/128), 256, SMEM_BYTES>>>(
        nullptr, hH, hL, W1H, W1L, b1, nullptr, mH, mL, 0, II, HD);

    // 5) eo = hmid @ W2[e] + b2[e], fused w-scaled atomic combine into comb
    mma_gemm<true,true,false,false,false,true>
        <<<dim3(MAXTILES, HD/128), 256, SMEM_BYTES>>>(
        nullptr, mH, mL, W2H, W2L, b2, comb_p, nullptr, nullptr, 0, HD, II);

    // 6) out = comb @ Wo + bo  (fp32 A path)
    mma_gemm<false,false,false,false,false,false>
        <<<dim3(DIM/128, NTOK/128), 256, SMEM_BYTES>>>(
        comb_p, nullptr, nullptr, WoH, WoL, bo, out, nullptr, nullptr, NTOK, DIM, DIM);
}

// round 14
// speedup vs baseline: 1.2641x; 1.2641x over previous
#include <cuda_runtime.h>
#include <cuda_bf16.h>
#include <math.h>
#include <stdint.h>

// ---------------------------------------------------------------------------
// Problem constants
// ---------------------------------------------------------------------------
#define BSZ   4
#define LEN   2048
#define DIM   1024
#define NH    8
#define NE    16
#define TOPK  2
#define HD    128
#define II    512
#define NTOK  (BSZ*LEN)    // 8192
#define NSUB  (NTOK*NH)    // 65536
#define NPAIR (NSUB*TOPK)  // 131072
#define MAXTILES (NPAIR/128 + NE)   // 1040

// ---------------------------------------------------------------------------
// Device scratch
// ---------------------------------------------------------------------------
__device__ float g_h   [(size_t)NTOK * DIM];
__device__ float g_comb[(size_t)NTOK * DIM];
__device__ float g_hmid[(size_t)NPAIR * II];
__device__ int   g_topi[NPAIR];
__device__ float g_topw[NPAIR];
__device__ int   g_perm[NPAIR];
__device__ float g_wslot[NPAIR];
__device__ int   g_counts[NE];
__device__ int   g_cursor[NE];
__device__ int   g_offsets[NE + 1];
__device__ int2  g_tilemap[MAXTILES];
__device__ int   g_ntiles;

// Prepacked weights: hi/lo bf16x2 (packed along k), transposed to [N][K/2]
__device__ uint32_t g_WmH[(size_t)DIM * DIM / 2];
__device__ uint32_t g_WmL[(size_t)DIM * DIM / 2];
__device__ uint32_t g_W1H[(size_t)NE * II * HD / 2];
__device__ uint32_t g_W1L[(size_t)NE * II * HD / 2];
__device__ uint32_t g_W2H[(size_t)NE * HD * II / 2];
__device__ uint32_t g_W2L[(size_t)NE * HD * II / 2];
__device__ uint32_t g_WoH[(size_t)DIM * DIM / 2];
__device__ uint32_t g_WoL[(size_t)DIM * DIM / 2];

__device__ __forceinline__ float gelu_exact(float x) {
    return 0.5f * x * (1.0f + erff(x * 0.70710678118654752440f));
}
__device__ __forceinline__ uint32_t pack_bf16x2(float e0, float e1) {
    uint32_t r;
    asm("cvt.rn.bf16x2.f32 %0, %1, %2;" : "=r"(r) : "f"(e1), "f"(e0));
    return r;
}
__device__ __forceinline__ float bf16_rt(float x) {
    return __bfloat162float(__float2bfloat16(x));
}
__device__ __forceinline__ void mma_bf16(float* d, const uint32_t* a, const uint32_t* b) {
    asm volatile(
        "mma.sync.aligned.m16n8k16.row.col.f32.bf16.bf16.f32 "
        "{%0,%1,%2,%3}, {%4,%5,%6,%7}, {%8,%9}, {%0,%1,%2,%3};\n"
        : "+f"(d[0]), "+f"(d[1]), "+f"(d[2]), "+f"(d[3])
        : "r"(a[0]), "r"(a[1]), "r"(a[2]), "r"(a[3]), "r"(b[0]), "r"(b[1]));
}
__device__ __forceinline__ void ldsm_x4(uint32_t& r0, uint32_t& r1,
                                        uint32_t& r2, uint32_t& r3, uint32_t addr) {
    asm volatile("ldmatrix.sync.aligned.m8n8.x4.shared.b16 {%0,%1,%2,%3}, [%4];"
                 : "=r"(r0), "=r"(r1), "=r"(r2), "=r"(r3) : "r"(addr));
}
__device__ __forceinline__ uint32_t smem_u32(const void* p) {
    return (uint32_t)__cvta_generic_to_shared(p);
}

#define CP16(dst, src) \
    asm volatile("cp.async.cg.shared.global [%0], [%1], 16;" :: "r"(dst), "l"(src))

// ---------------------------------------------------------------------------
// Weight prepack: B[K][N] (row-major, per expert) -> hi/lo [N][K/2] uint32
// ---------------------------------------------------------------------------
__global__ void prepack_kernel(const float* __restrict__ B,
                               uint32_t* __restrict__ Hi, uint32_t* __restrict__ Lo,
                               int K, int N)
{
    const int e = blockIdx.z;
    B  += (size_t)e * K * N;
    Hi += (size_t)e * N * (K / 2);
    Lo += (size_t)e * N * (K / 2);

    __shared__ float tile[64][33];
    const int tid = threadIdx.x;
    const int k0 = blockIdx.y * 64;
    const int n0 = blockIdx.x * 32;

#pragma unroll
    for (int i = 0; i < 8; i++) {
        const int row = i * 8 + (tid >> 5);
        const int col = tid & 31;
        tile[row][col] = B[(size_t)(k0 + row) * N + n0 + col];
    }
    __syncthreads();

#pragma unroll
    for (int j = 0; j < 4; j++) {
        const int nl = (tid >> 5) * 4 + j;
        const int kp = tid & 31;
        const float x0 = tile[2 * kp][nl];
        const float x1 = tile[2 * kp + 1][nl];
        const float h0 = bf16_rt(x0), h1 = bf16_rt(x1);
        const size_t o = (size_t)(n0 + nl) * (K / 2) + k0 / 2 + kp;
        Hi[o] = pack_bf16x2(h0, h1);
        Lo[o] = pack_bf16x2(x0 - h0, x1 - h1);
    }
}

// ---------------------------------------------------------------------------
// Zero the combine accumulator (float4 stream) + counters (first block).
// ---------------------------------------------------------------------------
__global__ void zero_comb() {
    int i = blockIdx.x * blockDim.x + threadIdx.x;
    reinterpret_cast<float4*>(g_comb)[i] = make_float4(0.f, 0.f, 0.f, 0.f);
    if (blockIdx.x == 0 && threadIdx.x < NE) {
        g_counts[threadIdx.x] = 0;
        g_cursor[threadIdx.x] = 0;
    }
}

// ---------------------------------------------------------------------------
// bf16-split tensor GEMM (R12: fp32-A reg prefetch + convert, A 2-stage smem,
// B 3-stage cp.async, one __syncthreads per k-tile; flat tile worklist).
// OUT_ATOMIC: epilogue scales by g_wslot[slot] and atomically accumulates
// into g_comb[g_perm[slot]*N + col] (fused MoE combine).
// ---------------------------------------------------------------------------
#define TSTRIDE 20
#define TILE_B  (128 * TSTRIDE * 4)       // 10240 bytes
#define SMEM_BYTES (10 * TILE_B)          // 102400

template<bool GROUPED, bool GATHER, bool DO_GELU, bool OUT_ATOMIC>
__global__ __launch_bounds__(256, 2)
void mma_gemm(const float* __restrict__ Asrc,
              const uint32_t* __restrict__ BpH, const uint32_t* __restrict__ BpL,
              const float* __restrict__ biasAll, float* __restrict__ Cout,
              int M, int N, int K)
{
    extern __shared__ __align__(16) uint32_t smem[];

    int rows = M, segBase = 0, m0, n0;
    const float* bias;
    if (GROUPED) {
        if ((int)blockIdx.x >= g_ntiles) return;
        const int2 tm = g_tilemap[blockIdx.x];
        const int e = tm.x;
        m0      = tm.y;
        rows    = g_counts[e];
        segBase = g_offsets[e];
        n0      = blockIdx.y * 128;
        BpH    += (size_t)e * N * (K / 2);
        BpL    += (size_t)e * N * (K / 2);
        bias    = biasAll + (size_t)e * N;
    } else {
        m0   = blockIdx.y * 128;
        n0   = blockIdx.x * 128;
        bias = biasAll;
    }

    const int tid  = threadIdx.x;
    const int lane = tid & 31;
    const int wid  = tid >> 5;
    const int g    = lane >> 2;
    const int tig  = lane & 3;
    const int wm   = (wid & 1) * 64;
    const int wn   = (wid >> 1) * 32;

    const uint32_t base = smem_u32(smem);

    // A loads: thread covers 4 rows, float4 at col (tid&7)*4
    const int acol = (tid & 7) * 4;
    const float* arow[4];
    bool aval[4];
#pragma unroll
    for (int v = 0; v < 4; v++) {
        const int r  = v * 32 + (tid >> 3);
        const int gr = m0 + r;
        if (GROUPED) {
            aval[v] = (gr < rows);
            int row = 0;
            if (aval[v]) row = GATHER ? g_perm[segBase + gr] : (segBase + gr);
            arow[v] = Asrc + (size_t)row * K + acol;
        } else {
            aval[v] = true;
            arow[v] = Asrc + (size_t)gr * K + acol;
        }
    }
    // A smem store offset within a stage (uint2 at [r][acol>>1])
    const uint32_t a_st = (((tid >> 3) * TSTRIDE) + (acol >> 1)) * 4;

    // B loads: thread covers col = tid>>1, 8 kpairs starting (tid&1)*8
    const int bcol  = tid >> 1;
    const int bkp   = (tid & 1) * 8;
    const uint32_t* bptrH = BpH + (size_t)(n0 + bcol) * (K / 2) + bkp;
    const uint32_t* bptrL = BpL + (size_t)(n0 + bcol) * (K / 2) + bkp;
    const uint32_t b_st = (bcol * TSTRIDE + bkp) * 4;

    // ldmatrix per-lane addresses (stage-local byte offsets)
    const uint32_t a_off = (((wm + (lane & 15)) * TSTRIDE) + ((lane >> 4) * 4)) * 4;
    const uint32_t b_off = (((wn + ((lane >> 4) & 1) * 8 + (lane & 7)) * TSTRIDE)
                            + (((lane >> 3) & 1) * 4)) * 4;

    float acc[4][4][4];
#pragma unroll
    for (int m = 0; m < 4; m++)
#pragma unroll
        for (int n = 0; n < 4; n++)
#pragma unroll
            for (int i = 0; i < 4; i++) acc[m][n][i] = 0.0f;

    const int KT = K / 32;

    auto issue_B = [&](int kt, int j) {
        const int kpo = kt * 16;
        const uint32_t dB = base + (4 + 2 * j) * TILE_B + b_st;
        CP16(dB,               bptrH + kpo);
        CP16(dB + 16,          bptrH + kpo + 4);
        CP16(dB + TILE_B,      bptrL + kpo);
        CP16(dB + TILE_B + 16, bptrL + kpo + 4);
        asm volatile("cp.async.commit_group;");
    };
    float4 areg[4];
    auto convert_A = [&](int sa) {
        const uint32_t sbase = base + sa * 2 * TILE_B;
#pragma unroll
        for (int v = 0; v < 4; v++) {
            const float hx = bf16_rt(areg[v].x), hy = bf16_rt(areg[v].y);
            const float hz = bf16_rt(areg[v].z), hw = bf16_rt(areg[v].w);
            uint2 hv, lv;
            hv.x = pack_bf16x2(hx, hy);
            hv.y = pack_bf16x2(hz, hw);
            lv.x = pack_bf16x2(areg[v].x - hx, areg[v].y - hy);
            lv.y = pack_bf16x2(areg[v].z - hz, areg[v].w - hw);
            const uint32_t d = sbase + a_st + v * 32 * TSTRIDE * 4;
            asm volatile("st.shared.v2.b32 [%0], {%1,%2};" :: "r"(d), "r"(hv.x), "r"(hv.y));
            asm volatile("st.shared.v2.b32 [%0], {%1,%2};"
                         :: "r"(d + TILE_B), "r"(lv.x), "r"(lv.y));
        }
    };
    auto fetch_A = [&](int kt) {
        const int ko = kt * 32;
#pragma unroll
        for (int v = 0; v < 4; v++) {
            areg[v] = make_float4(0.f, 0.f, 0.f, 0.f);
            if (aval[v]) areg[v] = *reinterpret_cast<const float4*>(arow[v] + ko);
        }
    };

    // ---- preloop ----
    fetch_A(0);
    convert_A(0);
    issue_B(0, 0);
    if (KT > 1) { fetch_A(1); issue_B(1, 1); }

    for (int kt = 0; kt < KT; kt++) {
        const int sA = kt & 1;
        const int sB = kt % 3;
        if (kt + 1 < KT) asm volatile("cp.async.wait_group 1;" ::: "memory");
        else             asm volatile("cp.async.wait_group 0;" ::: "memory");
        __syncthreads();

        if (kt + 2 < KT) issue_B(kt + 2, (kt + 2) % 3);

        const uint32_t aH_addr = base + sA * 2 * TILE_B + a_off;
        const uint32_t aL_addr = aH_addr + TILE_B;
        const uint32_t bH_addr = base + (4 + 2 * sB) * TILE_B + b_off;
        const uint32_t bL_addr = bH_addr + TILE_B;

#pragma unroll
        for (int ks = 0; ks < 2; ks++) {
            const uint32_t ksb = ks * 32;
            uint32_t bH[4][2], bL[4][2];
            ldsm_x4(bH[0][0], bH[0][1], bH[1][0], bH[1][1], bH_addr + ksb);
            ldsm_x4(bH[2][0], bH[2][1], bH[3][0], bH[3][1], bH_addr + ksb + 16 * TSTRIDE * 4);
            ldsm_x4(bL[0][0], bL[0][1], bL[1][0], bL[1][1], bL_addr + ksb);
            ldsm_x4(bL[2][0], bL[2][1], bL[3][0], bL[3][1], bL_addr + ksb + 16 * TSTRIDE * 4);
#pragma unroll
            for (int m = 0; m < 4; m++) {
                const uint32_t mb = m * 16 * TSTRIDE * 4;
                uint32_t aH[4], aL[4];
                ldsm_x4(aH[0], aH[1], aH[2], aH[3], aH_addr + mb + ksb);
                ldsm_x4(aL[0], aL[1], aL[2], aL[3], aL_addr + mb + ksb);
#pragma unroll
                for (int n = 0; n < 4; n++) {
                    mma_bf16(acc[m][n], aH, bH[n]);
                    mma_bf16(acc[m][n], aH, bL[n]);
                    mma_bf16(acc[m][n], aL, bH[n]);
                }
            }
        }

        if (kt + 1 < KT) {
            convert_A((kt + 1) & 1);
            if (kt + 2 < KT) fetch_A(kt + 2);
        }
    }

    // ---- epilogue ----
    if (OUT_ATOMIC) {
        // fused combine: Cout treated as [NSUB][N] accumulator
#pragma unroll
        for (int m = 0; m < 4; m++) {
            const int r0 = wm + m * 16 + g;
            int   tok[2]; float w[2]; bool ok[2];
#pragma unroll
            for (int h = 0; h < 2; h++) {
                const int gr = m0 + r0 + 8 * h;
                ok[h] = gr < rows;
                if (ok[h]) {
                    const int slot = segBase + gr;
                    tok[h] = g_perm[slot];
                    w[h]   = g_wslot[slot];
                } else { tok[h] = 0; w[h] = 0.f; }
            }
#pragma unroll
            for (int n = 0; n < 4; n++) {
                const int col = n0 + wn + n * 8 + 2 * tig;
                const float b0 = bias[col];
                const float b1 = bias[col + 1];
                if (ok[0]) {
                    float* p = Cout + (size_t)tok[0] * N + col;
                    atomicAdd(p,     w[0] * (acc[m][n][0] + b0));
                    atomicAdd(p + 1, w[0] * (acc[m][n][1] + b1));
                }
                if (ok[1]) {
                    float* p = Cout + (size_t)tok[1] * N + col;
                    atomicAdd(p,     w[1] * (acc[m][n][2] + b0));
                    atomicAdd(p + 1, w[1] * (acc[m][n][3] + b1));
                }
            }
        }
    } else {
#pragma unroll
        for (int n = 0; n < 4; n++) {
            const int col = n0 + wn + n * 8 + 2 * tig;
            const float b0 = bias[col];
            const float b1 = bias[col + 1];
#pragma unroll
            for (int m = 0; m < 4; m++) {
                const int r0 = wm + m * 16 + g;
                float v00 = acc[m][n][0] + b0;
                float v01 = acc[m][n][1] + b1;
                float v10 = acc[m][n][2] + b0;
                float v11 = acc[m][n][3] + b1;
                if (DO_GELU) {
                    v00 = gelu_exact(v00); v01 = gelu_exact(v01);
                    v10 = gelu_exact(v10); v11 = gelu_exact(v11);
                }
                if (GROUPED) {
                    if (m0 + r0 < rows) {
                        float* p = Cout + (size_t)(segBase + m0 + r0) * N + col;
                        *reinterpret_cast<float2*>(p) = make_float2(v00, v01);
                    }
                    if (m0 + r0 + 8 < rows) {
                        float* p = Cout + (size_t)(segBase + m0 + r0 + 8) * N + col;
                        *reinterpret_cast<float2*>(p) = make_float2(v10, v11);
                    }
                } else {
                    float* p0 = Cout + (size_t)(m0 + r0) * N + col;
                    float* p1 = Cout + (size_t)(m0 + r0 + 8) * N + col;
                    *reinterpret_cast<float2*>(p0) = make_float2(v00, v01);
                    *reinterpret_cast<float2*>(p1) = make_float2(v10, v11);
                }
            }
        }
    }
}

// ---------------------------------------------------------------------------
// Routing: one warp per sub-token + fused expert histogram (block-aggregated).
// ---------------------------------------------------------------------------
__global__ void routing_kernel(const float* __restrict__ emb)
{
    __shared__ int loc[NE];
    if (threadIdx.x < NE) loc[threadIdx.x] = 0;
    __syncthreads();

    const int warp = (blockIdx.x * blockDim.x + threadIdx.x) >> 5;
    const int lane = threadIdx.x & 31;

    const float* trow = g_h + (size_t)warp * HD;
    const float tv0 = trow[lane];
    const float tv1 = trow[lane + 32];
    const float tv2 = trow[lane + 64];
    const float tv3 = trow[lane + 96];

    float logits[NE];
#pragma unroll
    for (int e = 0; e < NE; e++) {
        float p = tv0 * emb[(lane      ) * NE + e]
                + tv1 * emb[(lane + 32 ) * NE + e]
                + tv2 * emb[(lane + 64 ) * NE + e]
                + tv3 * emb[(lane + 96 ) * NE + e];
#pragma unroll
        for (int s = 16; s > 0; s >>= 1) p += __shfl_xor_sync(0xffffffffu, p, s);
        logits[e] = p;
    }

    float mx = logits[0];
#pragma unroll
    for (int e = 1; e < NE; e++) mx = fmaxf(mx, logits[e]);
    float sum = 0.0f;
#pragma unroll
    for (int e = 0; e < NE; e++) { logits[e] = expf(logits[e] - mx); sum += logits[e]; }
    const float inv = 1.0f / sum;

    int i0 = 0; float v0 = logits[0];
#pragma unroll
    for (int e = 1; e < NE; e++) if (logits[e] > v0) { v0 = logits[e]; i0 = e; }
    int i1 = -1; float v1 = -1.0f;
#pragma unroll
    for (int e = 0; e < NE; e++) if (e != i0 && logits[e] > v1) { v1 = logits[e]; i1 = e; }

    if (lane == 0) {
        g_topi[2 * warp + 0] = i0;
        g_topi[2 * warp + 1] = i1;
        g_topw[2 * warp + 0] = v0 * inv;
        g_topw[2 * warp + 1] = v1 * inv;
        atomicAdd(&loc[i0], 1);
        atomicAdd(&loc[i1], 1);
    }
    __syncthreads();
    if (threadIdx.x < NE && loc[threadIdx.x])
        atomicAdd(&g_counts[threadIdx.x], loc[threadIdx.x]);
}

// ---------------------------------------------------------------------------
// Fused scan + tile-worklist build (single block).
// ---------------------------------------------------------------------------
__global__ void scan_build_kernel() {
    __shared__ int offs[NE + 1];
    if (threadIdx.x == 0) {
        int s = 0;
        for (int e = 0; e < NE; e++) { offs[e] = s; g_offsets[e] = s; s += g_counts[e]; }
        offs[NE] = s;
        g_offsets[NE] = s;
    }
    __syncthreads();
    const int e = threadIdx.x;
    if (e < NE) {
        int start = 0;
        for (int j = 0; j < e; j++) start += (g_counts[j] + 127) >> 7;
        const int nt = (g_counts[e] + 127) >> 7;
        for (int t = 0; t < nt; t++)
            g_tilemap[start + t] = make_int2(e, t << 7);
        if (e == NE - 1) g_ntiles = start + nt;
    }
}

// ---------------------------------------------------------------------------
// Scatter (warp/block-aggregated atomics); records perm + per-slot weight.
// ---------------------------------------------------------------------------
__global__ void scatter_kernel() {
    __shared__ int bcnt[NE];
    __shared__ int bbase[NE];
    if (threadIdx.x < NE) bcnt[threadIdx.x] = 0;
    __syncthreads();

    const int i    = blockIdx.x * blockDim.x + threadIdx.x;
    const int lane = threadIdx.x & 31;
    const int e    = g_topi[i];

    unsigned mask    = __match_any_sync(0xffffffffu, e);
    const int leader = __ffs(mask) - 1;
    const int lrank  = __popc(mask & ((1u << lane) - 1));
    int wbase = 0;
    if (lane == leader) wbase = atomicAdd(&bcnt[e], __popc(mask));
    wbase = __shfl_sync(0xffffffffu, wbase, leader);
    __syncthreads();

    if (threadIdx.x < NE)
        bbase[threadIdx.x] = bcnt[threadIdx.x]
            ? atomicAdd(&g_cursor[threadIdx.x], bcnt[threadIdx.x]) : 0;
    __syncthreads();

    const int slot = g_offsets[e] + bbase[e] + wbase + lrank;
    g_perm[slot]  = i >> 1;
    g_wslot[slot] = g_topw[i];
}

// ---------------------------------------------------------------------------
// Launch
// ---------------------------------------------------------------------------
extern "C" void kernel_launch(void* const* d_in, const int* in_sizes, int n_in,
                              void* d_out, int out_size)
{
    (void)in_sizes; (void)n_in; (void)out_size;
    const float* x   = (const float*)d_in[0];
    const float* Wm  = (const float*)d_in[1];
    const float* bm  = (const float*)d_in[2];
    const float* emb = (const float*)d_in[3];
    const float* W1  = (const float*)d_in[4];
    const float* b1  = (const float*)d_in[5];
    const float* W2  = (const float*)d_in[6];
    const float* b2  = (const float*)d_in[7];
    const float* Wo  = (const float*)d_in[8];
    const float* bo  = (const float*)d_in[9];
    float* out = (float*)d_out;

    float *h_p, *comb_p, *hmid_p;
    cudaGetSymbolAddress((void**)&h_p,    g_h);
    cudaGetSymbolAddress((void**)&comb_p, g_comb);
    cudaGetSymbolAddress((void**)&hmid_p, g_hmid);
    uint32_t *WmH, *WmL, *W1H, *W1L, *W2H, *W2L, *WoH, *WoL;
    cudaGetSymbolAddress((void**)&WmH, g_WmH); cudaGetSymbolAddress((void**)&WmL, g_WmL);
    cudaGetSymbolAddress((void**)&W1H, g_W1H); cudaGetSymbolAddress((void**)&W1L, g_W1L);
    cudaGetSymbolAddress((void**)&W2H, g_W2H); cudaGetSymbolAddress((void**)&W2L, g_W2L);
    cudaGetSymbolAddress((void**)&WoH, g_WoH); cudaGetSymbolAddress((void**)&WoL, g_WoL);

    cudaFuncSetAttribute(mma_gemm<false,false,false,false>,
                         cudaFuncAttributeMaxDynamicSharedMemorySize, SMEM_BYTES);
    cudaFuncSetAttribute(mma_gemm<true,true,true,false>,
                         cudaFuncAttributeMaxDynamicSharedMemorySize, SMEM_BYTES);
    cudaFuncSetAttribute(mma_gemm<true,false,false,true>,
                         cudaFuncAttributeMaxDynamicSharedMemorySize, SMEM_BYTES);

    // 0) prepack weights + zero combine accumulator + zero counters
    zero_comb<<<(NTOK * DIM / 4) / 256, 256>>>();
    prepack_kernel<<<dim3(DIM/32, DIM/64, 1),  256>>>(Wm, WmH, WmL, DIM, DIM);
    prepack_kernel<<<dim3(II/32,  HD/64,  NE), 256>>>(W1, W1H, W1L, HD, II);
    prepack_kernel<<<dim3(HD/32,  II/64,  NE), 256>>>(W2, W2H, W2L, II, HD);
    prepack_kernel<<<dim3(DIM/32, DIM/64, 1),  256>>>(Wo, WoH, WoL, DIM, DIM);

    // 1) h = x @ Wm + bm
    mma_gemm<false,false,false,false><<<dim3(DIM/128, NTOK/128), 256, SMEM_BYTES>>>(
        x, WmH, WmL, bm, h_p, NTOK, DIM, DIM);

    // 2) routing (+ fused histogram)
    routing_kernel<<<NSUB / 16, 512>>>(emb);

    // 3) expert bookkeeping (fused scan + tile worklist) + scatter
    scan_build_kernel<<<1, 32>>>();
    scatter_kernel<<<NPAIR / 256, 256>>>();

    // 4) hmid = gelu(t @ W1[e] + b1[e])   K=128, N=512 (gathered A)
    mma_gemm<true,true,true,false><<<dim3(MAXTILES, II/128), 256, SMEM_BYTES>>>(
        h_p, W1H, W1L, b1, hmid_p, 0, II, HD);

    // 5) eo = hmid @ W2[e] + b2[e], fused w-scaled atomic combine into comb
    mma_gemm<true,false,false,true><<<dim3(MAXTILES, HD/128), 256, SMEM_BYTES>>>(
        hmid_p, W2H, W2L, b2, comb_p, 0, HD, II);

    // 6) out = comb @ Wo + bo
    mma_gemm<false,false,false,false><<<dim3(DIM/128, NTOK/128), 256, SMEM_BYTES>>>(
        comb_p, WoH, WoL, bo, out, NTOK, DIM, DIM);
}

// round 15
// speedup vs baseline: 1.2824x; 1.0144x over previous
#include <cuda_runtime.h>
#include <cuda_bf16.h>
#include <math.h>
#include <stdint.h>

// ---------------------------------------------------------------------------
// Problem constants
// ---------------------------------------------------------------------------
#define BSZ   4
#define LEN   2048
#define DIM   1024
#define NH    8
#define NE    16
#define TOPK  2
#define HD    128
#define II    512
#define NTOK  (BSZ*LEN)    // 8192
#define NSUB  (NTOK*NH)    // 65536
#define NPAIR (NSUB*TOPK)  // 131072
#define MAXTILES (NPAIR/128 + NE)   // 1040

// ---------------------------------------------------------------------------
// Device scratch
// ---------------------------------------------------------------------------
__device__ float g_h   [(size_t)NTOK * DIM];
__device__ float g_comb[(size_t)NTOK * DIM];
__device__ float g_hmid[(size_t)NPAIR * II];
__device__ int   g_topi[NPAIR];
__device__ float g_topw[NPAIR];
__device__ int   g_perm[NPAIR];
__device__ float g_wslot[NPAIR];
__device__ int   g_counts[NE];
__device__ int   g_cursor[NE];
__device__ int   g_offsets[NE + 1];
__device__ int2  g_tilemap[MAXTILES];
__device__ int   g_ntiles;

// Prepacked weights: hi/lo bf16x2 (packed along k), transposed to [N][K/2]
__device__ uint32_t g_WmH[(size_t)DIM * DIM / 2];
__device__ uint32_t g_WmL[(size_t)DIM * DIM / 2];
__device__ uint32_t g_W1H[(size_t)NE * II * HD / 2];
__device__ uint32_t g_W1L[(size_t)NE * II * HD / 2];
__device__ uint32_t g_W2H[(size_t)NE * HD * II / 2];
__device__ uint32_t g_W2L[(size_t)NE * HD * II / 2];
__device__ uint32_t g_WoH[(size_t)DIM * DIM / 2];
__device__ uint32_t g_WoL[(size_t)DIM * DIM / 2];

__device__ __forceinline__ float gelu_exact(float x) {
    return 0.5f * x * (1.0f + erff(x * 0.70710678118654752440f));
}
__device__ __forceinline__ uint32_t pack_bf16x2(float e0, float e1) {
    uint32_t r;
    asm("cvt.rn.bf16x2.f32 %0, %1, %2;" : "=r"(r) : "f"(e1), "f"(e0));
    return r;
}
__device__ __forceinline__ float bf16_rt(float x) {
    return __bfloat162float(__float2bfloat16(x));
}
__device__ __forceinline__ void mma_bf16(float* d, const uint32_t* a, const uint32_t* b) {
    asm volatile(
        "mma.sync.aligned.m16n8k16.row.col.f32.bf16.bf16.f32 "
        "{%0,%1,%2,%3}, {%4,%5,%6,%7}, {%8,%9}, {%0,%1,%2,%3};\n"
        : "+f"(d[0]), "+f"(d[1]), "+f"(d[2]), "+f"(d[3])
        : "r"(a[0]), "r"(a[1]), "r"(a[2]), "r"(a[3]), "r"(b[0]), "r"(b[1]));
}
__device__ __forceinline__ void ldsm_x4(uint32_t& r0, uint32_t& r1,
                                        uint32_t& r2, uint32_t& r3, uint32_t addr) {
    asm volatile("ldmatrix.sync.aligned.m8n8.x4.shared.b16 {%0,%1,%2,%3}, [%4];"
                 : "=r"(r0), "=r"(r1), "=r"(r2), "=r"(r3) : "r"(addr));
}
__device__ __forceinline__ uint32_t smem_u32(const void* p) {
    return (uint32_t)__cvta_generic_to_shared(p);
}

#define CP16(dst, src) \
    asm volatile("cp.async.cg.shared.global [%0], [%1], 16;" :: "r"(dst), "l"(src))

// ---------------------------------------------------------------------------
// Weight prepack: B[K][N] (row-major, per expert) -> hi/lo [N][K/2] uint32
// ---------------------------------------------------------------------------
__global__ void prepack_kernel(const float* __restrict__ B,
                               uint32_t* __restrict__ Hi, uint32_t* __restrict__ Lo,
                               int K, int N)
{
    const int e = blockIdx.z;
    B  += (size_t)e * K * N;
    Hi += (size_t)e * N * (K / 2);
    Lo += (size_t)e * N * (K / 2);

    __shared__ float tile[64][33];
    const int tid = threadIdx.x;
    const int k0 = blockIdx.y * 64;
    const int n0 = blockIdx.x * 32;

#pragma unroll
    for (int i = 0; i < 8; i++) {
        const int row = i * 8 + (tid >> 5);
        const int col = tid & 31;
        tile[row][col] = B[(size_t)(k0 + row) * N + n0 + col];
    }
    __syncthreads();

#pragma unroll
    for (int j = 0; j < 4; j++) {
        const int nl = (tid >> 5) * 4 + j;
        const int kp = tid & 31;
        const float x0 = tile[2 * kp][nl];
        const float x1 = tile[2 * kp + 1][nl];
        const float h0 = bf16_rt(x0), h1 = bf16_rt(x1);
        const size_t o = (size_t)(n0 + nl) * (K / 2) + k0 / 2 + kp;
        Hi[o] = pack_bf16x2(h0, h1);
        Lo[o] = pack_bf16x2(x0 - h0, x1 - h1);
    }
}

// ---------------------------------------------------------------------------
// Zero the combine accumulator (float4 stream).
// ---------------------------------------------------------------------------
__global__ void zero_comb() {
    int i = blockIdx.x * blockDim.x + threadIdx.x;
    reinterpret_cast<float4*>(g_comb)[i] = make_float4(0.f, 0.f, 0.f, 0.f);
}

// ---------------------------------------------------------------------------
// bf16-split tensor GEMM (flat tile worklist for GROUPED; fp32-A reg prefetch
// + convert; A 2-stage smem, B 3-stage cp.async, one __syncthreads per tile).
// OUT_ATOMIC: epilogue scales by g_wslot[slot] and atomically accumulates
// into g_comb[g_perm[slot]*N + col] (fused MoE combine).
// ---------------------------------------------------------------------------
#define TSTRIDE 20
#define TILE_B  (128 * TSTRIDE * 4)       // 10240 bytes
#define SMEM_BYTES (10 * TILE_B)          // 102400

template<bool GROUPED, bool GATHER, bool DO_GELU, bool OUT_ATOMIC>
__global__ __launch_bounds__(256, 2)
void mma_gemm(const float* __restrict__ Asrc,
              const uint32_t* __restrict__ BpH, const uint32_t* __restrict__ BpL,
              const float* __restrict__ biasAll, float* __restrict__ Cout,
              int M, int N, int K)
{
    extern __shared__ __align__(16) uint32_t smem[];

    int rows = M, segBase = 0, m0, n0;
    const float* bias;
    if (GROUPED) {
        if ((int)blockIdx.x >= g_ntiles) return;
        const int2 tm = g_tilemap[blockIdx.x];
        const int e = tm.x;
        m0      = tm.y;
        rows    = g_counts[e];
        segBase = g_offsets[e];
        n0      = blockIdx.y * 128;
        BpH    += (size_t)e * N * (K / 2);
        BpL    += (size_t)e * N * (K / 2);
        bias    = biasAll + (size_t)e * N;
    } else {
        m0   = blockIdx.y * 128;
        n0   = blockIdx.x * 128;
        bias = biasAll;
    }

    const int tid  = threadIdx.x;
    const int lane = tid & 31;
    const int wid  = tid >> 5;
    const int g    = lane >> 2;
    const int tig  = lane & 3;
    const int wm   = (wid & 1) * 64;
    const int wn   = (wid >> 1) * 32;

    const uint32_t base = smem_u32(smem);

    // A loads: thread covers 4 rows, float4 at col (tid&7)*4
    const int acol = (tid & 7) * 4;
    const float* arow[4];
    bool aval[4];
#pragma unroll
    for (int v = 0; v < 4; v++) {
        const int r  = v * 32 + (tid >> 3);
        const int gr = m0 + r;
        if (GROUPED) {
            aval[v] = (gr < rows);
            int row = 0;
            if (aval[v]) row = GATHER ? g_perm[segBase + gr] : (segBase + gr);
            arow[v] = Asrc + (size_t)row * K + acol;
        } else {
            aval[v] = true;
            arow[v] = Asrc + (size_t)gr * K + acol;
        }
    }
    // A smem store offset within a stage (uint2 at [r][acol>>1])
    const uint32_t a_st = (((tid >> 3) * TSTRIDE) + (acol >> 1)) * 4;

    // B loads: thread covers col = tid>>1, 8 kpairs starting (tid&1)*8
    const int bcol  = tid >> 1;
    const int bkp   = (tid & 1) * 8;
    const uint32_t* bptrH = BpH + (size_t)(n0 + bcol) * (K / 2) + bkp;
    const uint32_t* bptrL = BpL + (size_t)(n0 + bcol) * (K / 2) + bkp;
    const uint32_t b_st = (bcol * TSTRIDE + bkp) * 4;

    // ldmatrix per-lane addresses (stage-local byte offsets)
    const uint32_t a_off = (((wm + (lane & 15)) * TSTRIDE) + ((lane >> 4) * 4)) * 4;
    const uint32_t b_off = (((wn + ((lane >> 4) & 1) * 8 + (lane & 7)) * TSTRIDE)
                            + (((lane >> 3) & 1) * 4)) * 4;

    float acc[4][4][4];
#pragma unroll
    for (int m = 0; m < 4; m++)
#pragma unroll
        for (int n = 0; n < 4; n++)
#pragma unroll
            for (int i = 0; i < 4; i++) acc[m][n][i] = 0.0f;

    const int KT = K / 32;

    auto issue_B = [&](int kt, int j) {
        const int kpo = kt * 16;
        const uint32_t dB = base + (4 + 2 * j) * TILE_B + b_st;
        CP16(dB,               bptrH + kpo);
        CP16(dB + 16,          bptrH + kpo + 4);
        CP16(dB + TILE_B,      bptrL + kpo);
        CP16(dB + TILE_B + 16, bptrL + kpo + 4);
        asm volatile("cp.async.commit_group;");
    };
    float4 areg[4];
    auto convert_A = [&](int sa) {
        const uint32_t sbase = base + sa * 2 * TILE_B;
#pragma unroll
        for (int v = 0; v < 4; v++) {
            const float hx = bf16_rt(areg[v].x), hy = bf16_rt(areg[v].y);
            const float hz = bf16_rt(areg[v].z), hw = bf16_rt(areg[v].w);
            uint2 hv, lv;
            hv.x = pack_bf16x2(hx, hy);
            hv.y = pack_bf16x2(hz, hw);
            lv.x = pack_bf16x2(areg[v].x - hx, areg[v].y - hy);
            lv.y = pack_bf16x2(areg[v].z - hz, areg[v].w - hw);
            const uint32_t d = sbase + a_st + v * 32 * TSTRIDE * 4;
            asm volatile("st.shared.v2.b32 [%0], {%1,%2};" :: "r"(d), "r"(hv.x), "r"(hv.y));
            asm volatile("st.shared.v2.b32 [%0], {%1,%2};"
                         :: "r"(d + TILE_B), "r"(lv.x), "r"(lv.y));
        }
    };
    auto fetch_A = [&](int kt) {
        const int ko = kt * 32;
#pragma unroll
        for (int v = 0; v < 4; v++) {
            areg[v] = make_float4(0.f, 0.f, 0.f, 0.f);
            if (aval[v]) areg[v] = *reinterpret_cast<const float4*>(arow[v] + ko);
        }
    };

    // ---- preloop ----
    fetch_A(0);
    convert_A(0);
    issue_B(0, 0);
    if (KT > 1) { fetch_A(1); issue_B(1, 1); }

    for (int kt = 0; kt < KT; kt++) {
        const int sA = kt & 1;
        const int sB = kt % 3;
        if (kt + 1 < KT) asm volatile("cp.async.wait_group 1;" ::: "memory");
        else             asm volatile("cp.async.wait_group 0;" ::: "memory");
        __syncthreads();

        if (kt + 2 < KT) issue_B(kt + 2, (kt + 2) % 3);

        const uint32_t aH_addr = base + sA * 2 * TILE_B + a_off;
        const uint32_t aL_addr = aH_addr + TILE_B;
        const uint32_t bH_addr = base + (4 + 2 * sB) * TILE_B + b_off;
        const uint32_t bL_addr = bH_addr + TILE_B;

#pragma unroll
        for (int ks = 0; ks < 2; ks++) {
            const uint32_t ksb = ks * 32;
            uint32_t bH[4][2], bL[4][2];
            ldsm_x4(bH[0][0], bH[0][1], bH[1][0], bH[1][1], bH_addr + ksb);
            ldsm_x4(bH[2][0], bH[2][1], bH[3][0], bH[3][1], bH_addr + ksb + 16 * TSTRIDE * 4);
            ldsm_x4(bL[0][0], bL[0][1], bL[1][0], bL[1][1], bL_addr + ksb);
            ldsm_x4(bL[2][0], bL[2][1], bL[3][0], bL[3][1], bL_addr + ksb + 16 * TSTRIDE * 4);
#pragma unroll
            for (int m = 0; m < 4; m++) {
                const uint32_t mb = m * 16 * TSTRIDE * 4;
                uint32_t aH[4], aL[4];
                ldsm_x4(aH[0], aH[1], aH[2], aH[3], aH_addr + mb + ksb);
                ldsm_x4(aL[0], aL[1], aL[2], aL[3], aL_addr + mb + ksb);
#pragma unroll
                for (int n = 0; n < 4; n++) {
                    mma_bf16(acc[m][n], aH, bH[n]);
                    mma_bf16(acc[m][n], aH, bL[n]);
                    mma_bf16(acc[m][n], aL, bH[n]);
                }
            }
        }

        if (kt + 1 < KT) {
            convert_A((kt + 1) & 1);
            if (kt + 2 < KT) fetch_A(kt + 2);
        }
    }

    // ---- epilogue ----
    if (OUT_ATOMIC) {
        // fused combine: Cout treated as [NSUB][N] accumulator
#pragma unroll
        for (int m = 0; m < 4; m++) {
            const int r0 = wm + m * 16 + g;
            int   tok[2]; float w[2]; bool ok[2];
#pragma unroll
            for (int h = 0; h < 2; h++) {
                const int gr = m0 + r0 + 8 * h;
                ok[h] = gr < rows;
                if (ok[h]) {
                    const int slot = segBase + gr;
                    tok[h] = g_perm[slot];
                    w[h]   = g_wslot[slot];
                } else { tok[h] = 0; w[h] = 0.f; }
            }
#pragma unroll
            for (int n = 0; n < 4; n++) {
                const int col = n0 + wn + n * 8 + 2 * tig;
                const float b0 = bias[col];
                const float b1 = bias[col + 1];
                if (ok[0]) {
                    float* p = Cout + (size_t)tok[0] * N + col;
                    atomicAdd(p,     w[0] * (acc[m][n][0] + b0));
                    atomicAdd(p + 1, w[0] * (acc[m][n][1] + b1));
                }
                if (ok[1]) {
                    float* p = Cout + (size_t)tok[1] * N + col;
                    atomicAdd(p,     w[1] * (acc[m][n][2] + b0));
                    atomicAdd(p + 1, w[1] * (acc[m][n][3] + b1));
                }
            }
        }
    } else {
#pragma unroll
        for (int n = 0; n < 4; n++) {
            const int col = n0 + wn + n * 8 + 2 * tig;
            const float b0 = bias[col];
            const float b1 = bias[col + 1];
#pragma unroll
            for (int m = 0; m < 4; m++) {
                const int r0 = wm + m * 16 + g;
                float v00 = acc[m][n][0] + b0;
                float v01 = acc[m][n][1] + b1;
                float v10 = acc[m][n][2] + b0;
                float v11 = acc[m][n][3] + b1;
                if (DO_GELU) {
                    v00 = gelu_exact(v00); v01 = gelu_exact(v01);
                    v10 = gelu_exact(v10); v11 = gelu_exact(v11);
                }
                if (GROUPED) {
                    if (m0 + r0 < rows) {
                        float* p = Cout + (size_t)(segBase + m0 + r0) * N + col;
                        *reinterpret_cast<float2*>(p) = make_float2(v00, v01);
                    }
                    if (m0 + r0 + 8 < rows) {
                        float* p = Cout + (size_t)(segBase + m0 + r0 + 8) * N + col;
                        *reinterpret_cast<float2*>(p) = make_float2(v10, v11);
                    }
                } else {
                    float* p0 = Cout + (size_t)(m0 + r0) * N + col;
                    float* p1 = Cout + (size_t)(m0 + r0 + 8) * N + col;
                    *reinterpret_cast<float2*>(p0) = make_float2(v00, v01);
                    *reinterpret_cast<float2*>(p1) = make_float2(v10, v11);
                }
            }
        }
    }
}

// ---------------------------------------------------------------------------
// Routing: one warp per sub-token + fused expert histogram (block-aggregated).
// ---------------------------------------------------------------------------
__global__ void routing_kernel(const float* __restrict__ emb)
{
    __shared__ int loc[NE];
    if (threadIdx.x < NE) loc[threadIdx.x] = 0;
    __syncthreads();

    const int warp = (blockIdx.x * blockDim.x + threadIdx.x) >> 5;
    const int lane = threadIdx.x & 31;

    const float* trow = g_h + (size_t)warp * HD;
    const float tv0 = trow[lane];
    const float tv1 = trow[lane + 32];
    const float tv2 = trow[lane + 64];
    const float tv3 = trow[lane + 96];

    float logits[NE];
#pragma unroll
    for (int e = 0; e < NE; e++) {
        float p = tv0 * emb[(lane      ) * NE + e]
                + tv1 * emb[(lane + 32 ) * NE + e]
                + tv2 * emb[(lane + 64 ) * NE + e]
                + tv3 * emb[(lane + 96 ) * NE + e];
#pragma unroll
        for (int s = 16; s > 0; s >>= 1) p += __shfl_xor_sync(0xffffffffu, p, s);
        logits[e] = p;
    }

    float mx = logits[0];
#pragma unroll
    for (int e = 1; e < NE; e++) mx = fmaxf(mx, logits[e]);
    float sum = 0.0f;
#pragma unroll
    for (int e = 0; e < NE; e++) { logits[e] = expf(logits[e] - mx); sum += logits[e]; }
    const float inv = 1.0f / sum;

    int i0 = 0; float v0 = logits[0];
#pragma unroll
    for (int e = 1; e < NE; e++) if (logits[e] > v0) { v0 = logits[e]; i0 = e; }
    int i1 = -1; float v1 = -1.0f;
#pragma unroll
    for (int e = 0; e < NE; e++) if (e != i0 && logits[e] > v1) { v1 = logits[e]; i1 = e; }

    if (lane == 0) {
        g_topi[2 * warp + 0] = i0;
        g_topi[2 * warp + 1] = i1;
        g_topw[2 * warp + 0] = v0 * inv;
        g_topw[2 * warp + 1] = v1 * inv;
        atomicAdd(&loc[i0], 1);
        atomicAdd(&loc[i1], 1);
    }
    __syncthreads();
    if (threadIdx.x < NE && loc[threadIdx.x])
        atomicAdd(&g_counts[threadIdx.x], loc[threadIdx.x]);
}

// ---------------------------------------------------------------------------
// Routing bookkeeping
// ---------------------------------------------------------------------------
__global__ void zero_counts() {
    int i = threadIdx.x;
    if (i < NE) { g_counts[i] = 0; g_cursor[i] = 0; }
}
__global__ void scan_kernel() {
    int s = 0;
    for (int e = 0; e < NE; e++) { g_offsets[e] = s; s += g_counts[e]; }
    g_offsets[NE] = s;
}
__global__ void build_tiles() {
    const int e = threadIdx.x;
    if (e >= NE) return;
    int start = 0;
#pragma unroll
    for (int j = 0; j < NE; j++) {
        int tj = (g_counts[j] + 127) >> 7;
        if (j < e) start += tj;
        if (e == NE - 1 && j == NE - 1) g_ntiles = start + tj;
    }
    const int nt = (g_counts[e] + 127) >> 7;
    for (int t = 0; t < nt; t++)
        g_tilemap[start + t] = make_int2(e, t << 7);
}
__global__ void scatter_kernel() {
    __shared__ int bcnt[NE];
    __shared__ int bbase[NE];
    if (threadIdx.x < NE) bcnt[threadIdx.x] = 0;
    __syncthreads();

    const int i    = blockIdx.x * blockDim.x + threadIdx.x;
    const int lane = threadIdx.x & 31;
    const int e    = g_topi[i];

    unsigned mask    = __match_any_sync(0xffffffffu, e);
    const int leader = __ffs(mask) - 1;
    const int lrank  = __popc(mask & ((1u << lane) - 1));
    int wbase = 0;
    if (lane == leader) wbase = atomicAdd(&bcnt[e], __popc(mask));
    wbase = __shfl_sync(0xffffffffu, wbase, leader);
    __syncthreads();

    if (threadIdx.x < NE)
        bbase[threadIdx.x] = bcnt[threadIdx.x]
            ? atomicAdd(&g_cursor[threadIdx.x], bcnt[threadIdx.x]) : 0;
    __syncthreads();

    const int slot = g_offsets[e] + bbase[e] + wbase + lrank;
    g_perm[slot]  = i >> 1;
    g_wslot[slot] = g_topw[i];
}

// ---------------------------------------------------------------------------
// Launch
// ---------------------------------------------------------------------------
extern "C" void kernel_launch(void* const* d_in, const int* in_sizes, int n_in,
                              void* d_out, int out_size)
{
    (void)in_sizes; (void)n_in; (void)out_size;
    const float* x   = (const float*)d_in[0];
    const float* Wm  = (const float*)d_in[1];
    const float* bm  = (const float*)d_in[2];
    const float* emb = (const float*)d_in[3];
    const float* W1  = (const float*)d_in[4];
    const float* b1  = (const float*)d_in[5];
    const float* W2  = (const float*)d_in[6];
    const float* b2  = (const float*)d_in[7];
    const float* Wo  = (const float*)d_in[8];
    const float* bo  = (const float*)d_in[9];
    float* out = (float*)d_out;

    float *h_p, *comb_p, *hmid_p;
    cudaGetSymbolAddress((void**)&h_p,    g_h);
    cudaGetSymbolAddress((void**)&comb_p, g_comb);
    cudaGetSymbolAddress((void**)&hmid_p, g_hmid);
    uint32_t *WmH, *WmL, *W1H, *W1L, *W2H, *W2L, *WoH, *WoL;
    cudaGetSymbolAddress((void**)&WmH, g_WmH); cudaGetSymbolAddress((void**)&WmL, g_WmL);
    cudaGetSymbolAddress((void**)&W1H, g_W1H); cudaGetSymbolAddress((void**)&W1L, g_W1L);
    cudaGetSymbolAddress((void**)&W2H, g_W2H); cudaGetSymbolAddress((void**)&W2L, g_W2L);
    cudaGetSymbolAddress((void**)&WoH, g_WoH); cudaGetSymbolAddress((void**)&WoL, g_WoL);

    cudaFuncSetAttribute(mma_gemm<false,false,false,false>,
                         cudaFuncAttributeMaxDynamicSharedMemorySize, SMEM_BYTES);
    cudaFuncSetAttribute(mma_gemm<true,true,true,false>,
                         cudaFuncAttributeMaxDynamicSharedMemorySize, SMEM_BYTES);
    cudaFuncSetAttribute(mma_gemm<true,false,false,true>,
                         cudaFuncAttributeMaxDynamicSharedMemorySize, SMEM_BYTES);

    // 0) prepack weights + zero combine accumulator + zero counts
    zero_comb<<<(NTOK * DIM / 4) / 256, 256>>>();
    zero_counts<<<1, 32>>>();
    prepack_kernel<<<dim3(DIM/32, DIM/64, 1),  256>>>(Wm, WmH, WmL, DIM, DIM);
    prepack_kernel<<<dim3(II/32,  HD/64,  NE), 256>>>(W1, W1H, W1L, HD, II);
    prepack_kernel<<<dim3(HD/32,  II/64,  NE), 256>>>(W2, W2H, W2L, II, HD);
    prepack_kernel<<<dim3(DIM/32, DIM/64, 1),  256>>>(Wo, WoH, WoL, DIM, DIM);

    // 1) h = x @ Wm + bm
    mma_gemm<false,false,false,false><<<dim3(DIM/128, NTOK/128), 256, SMEM_BYTES>>>(
        x, WmH, WmL, bm, h_p, NTOK, DIM, DIM);

    // 2) routing (+ fused histogram)
    routing_kernel<<<NSUB / 16, 512>>>(emb);

    // 3) expert bookkeeping + tile worklist
    scan_kernel<<<1, 1>>>();
    build_tiles<<<1, NE>>>();
    scatter_kernel<<<NPAIR / 256, 256>>>();

    // 4) hmid = gelu(t @ W1[e] + b1[e])   K=128, N=512 (gathered A)
    mma_gemm<true,true,true,false><<<dim3(MAXTILES, II/128), 256, SMEM_BYTES>>>(
        h_p, W1H, W1L, b1, hmid_p, 0, II, HD);

    // 5) eo = hmid @ W2[e] + b2[e], fused w-scaled atomic combine into comb
    mma_gemm<true,false,false,true><<<dim3(MAXTILES, HD/128), 256, SMEM_BYTES>>>(
        hmid_p, W2H, W2L, b2, comb_p, 0, HD, II);

    // 6) out = comb @ Wo + bo
    mma_gemm<false,false,false,false><<<dim3(DIM/128, NTOK/128), 256, SMEM_BYTES>>>(
        comb_p, WoH, WoL, bo, out, NTOK, DIM, DIM);
}

// round 16
// speedup vs baseline: 1.2884x; 1.0047x over previous
#include <cuda_runtime.h>
#include <cuda_bf16.h>
#include <math.h>
#include <stdint.h>

// ---------------------------------------------------------------------------
// Problem constants
// ---------------------------------------------------------------------------
#define BSZ   4
#define LEN   2048
#define DIM   1024
#define NH    8
#define NE    16
#define TOPK  2
#define HD    128
#define II    512
#define NTOK  (BSZ*LEN)    // 8192
#define NSUB  (NTOK*NH)    // 65536
#define NPAIR (NSUB*TOPK)  // 131072
#define MAXTILES (NPAIR/128 + NE)   // 1040

// ---------------------------------------------------------------------------
// Device scratch
// ---------------------------------------------------------------------------
__device__ float g_h   [(size_t)NTOK * DIM];
__device__ float g_comb[(size_t)NTOK * DIM];
__device__ float g_hmid[(size_t)NPAIR * II];
__device__ int   g_topi[NPAIR];
__device__ float g_topw[NPAIR];
__device__ int   g_perm[NPAIR];
__device__ float g_wslot[NPAIR];
__device__ int   g_counts[NE];
__device__ int   g_cursor[NE];
__device__ int   g_offsets[NE + 1];
__device__ int2  g_tilemap[MAXTILES];
__device__ int   g_ntiles;

// Prepacked weights: hi/lo bf16x2 (packed along k), transposed to [N][K/2]
__device__ uint32_t g_WmH[(size_t)DIM * DIM / 2];
__device__ uint32_t g_WmL[(size_t)DIM * DIM / 2];
__device__ uint32_t g_W1H[(size_t)NE * II * HD / 2];
__device__ uint32_t g_W1L[(size_t)NE * II * HD / 2];
__device__ uint32_t g_W2H[(size_t)NE * HD * II / 2];
__device__ uint32_t g_W2L[(size_t)NE * HD * II / 2];
__device__ uint32_t g_WoH[(size_t)DIM * DIM / 2];
__device__ uint32_t g_WoL[(size_t)DIM * DIM / 2];

__device__ __forceinline__ float gelu_exact(float x) {
    return 0.5f * x * (1.0f + erff(x * 0.70710678118654752440f));
}
__device__ __forceinline__ uint32_t pack_bf16x2(float e0, float e1) {
    uint32_t r;
    asm("cvt.rn.bf16x2.f32 %0, %1, %2;" : "=r"(r) : "f"(e1), "f"(e0));
    return r;
}
__device__ __forceinline__ float bf16_rt(float x) {
    return __bfloat162float(__float2bfloat16(x));
}
__device__ __forceinline__ void mma_bf16(float* d, const uint32_t* a, const uint32_t* b) {
    asm volatile(
        "mma.sync.aligned.m16n8k16.row.col.f32.bf16.bf16.f32 "
        "{%0,%1,%2,%3}, {%4,%5,%6,%7}, {%8,%9}, {%0,%1,%2,%3};\n"
        : "+f"(d[0]), "+f"(d[1]), "+f"(d[2]), "+f"(d[3])
        : "r"(a[0]), "r"(a[1]), "r"(a[2]), "r"(a[3]), "r"(b[0]), "r"(b[1]));
}
__device__ __forceinline__ void ldsm_x4(uint32_t& r0, uint32_t& r1,
                                        uint32_t& r2, uint32_t& r3, uint32_t addr) {
    asm volatile("ldmatrix.sync.aligned.m8n8.x4.shared.b16 {%0,%1,%2,%3}, [%4];"
                 : "=r"(r0), "=r"(r1), "=r"(r2), "=r"(r3) : "r"(addr));
}
__device__ __forceinline__ uint32_t smem_u32(const void* p) {
    return (uint32_t)__cvta_generic_to_shared(p);
}

#define CP16(dst, src) \
    asm volatile("cp.async.cg.shared.global [%0], [%1], 16;" :: "r"(dst), "l"(src))

// ---------------------------------------------------------------------------
// Weight prepack: B[K][N] (row-major, per expert) -> hi/lo [N][K/2] uint32
// ---------------------------------------------------------------------------
__global__ void prepack_kernel(const float* __restrict__ B,
                               uint32_t* __restrict__ Hi, uint32_t* __restrict__ Lo,
                               int K, int N)
{
    const int e = blockIdx.z;
    B  += (size_t)e * K * N;
    Hi += (size_t)e * N * (K / 2);
    Lo += (size_t)e * N * (K / 2);

    __shared__ float tile[64][33];
    const int tid = threadIdx.x;
    const int k0 = blockIdx.y * 64;
    const int n0 = blockIdx.x * 32;

#pragma unroll
    for (int i = 0; i < 8; i++) {
        const int row = i * 8 + (tid >> 5);
        const int col = tid & 31;
        tile[row][col] = B[(size_t)(k0 + row) * N + n0 + col];
    }
    __syncthreads();

#pragma unroll
    for (int j = 0; j < 4; j++) {
        const int nl = (tid >> 5) * 4 + j;
        const int kp = tid & 31;
        const float x0 = tile[2 * kp][nl];
        const float x1 = tile[2 * kp + 1][nl];
        const float h0 = bf16_rt(x0), h1 = bf16_rt(x1);
        const size_t o = (size_t)(n0 + nl) * (K / 2) + k0 / 2 + kp;
        Hi[o] = pack_bf16x2(h0, h1);
        Lo[o] = pack_bf16x2(x0 - h0, x1 - h1);
    }
}

// ---------------------------------------------------------------------------
// Zero the combine accumulator (float4 stream).
// ---------------------------------------------------------------------------
__global__ void zero_comb() {
    int i = blockIdx.x * blockDim.x + threadIdx.x;
    reinterpret_cast<float4*>(g_comb)[i] = make_float4(0.f, 0.f, 0.f, 0.f);
}

// ---------------------------------------------------------------------------
// bf16-split tensor GEMM (R12 engine).
// GROUPED grid is TRANSPOSED: blockIdx.x = n-tile (fastest), blockIdx.y =
// flat worklist tile — so CTAs sharing gathered A rows are launch-adjacent
// and A gathers hit L2 instead of DRAM.
// OUT_ATOMIC: epilogue scales by g_wslot[slot] and atomically accumulates
// into g_comb[g_perm[slot]*N + col] (fused MoE combine).
// ---------------------------------------------------------------------------
#define TSTRIDE 20
#define TILE_B  (128 * TSTRIDE * 4)       // 10240 bytes
#define SMEM_BYTES (10 * TILE_B)          // 102400

template<bool GROUPED, bool GATHER, bool DO_GELU, bool OUT_ATOMIC>
__global__ __launch_bounds__(256, 2)
void mma_gemm(const float* __restrict__ Asrc,
              const uint32_t* __restrict__ BpH, const uint32_t* __restrict__ BpL,
              const float* __restrict__ biasAll, float* __restrict__ Cout,
              int M, int N, int K)
{
    extern __shared__ __align__(16) uint32_t smem[];

    int rows = M, segBase = 0, m0, n0;
    const float* bias;
    if (GROUPED) {
        if ((int)blockIdx.y >= g_ntiles) return;
        const int2 tm = g_tilemap[blockIdx.y];
        const int e = tm.x;
        m0      = tm.y;
        rows    = g_counts[e];
        segBase = g_offsets[e];
        n0      = blockIdx.x * 128;
        BpH    += (size_t)e * N * (K / 2);
        BpL    += (size_t)e * N * (K / 2);
        bias    = biasAll + (size_t)e * N;
    } else {
        m0   = blockIdx.y * 128;
        n0   = blockIdx.x * 128;
        bias = biasAll;
    }

    const int tid  = threadIdx.x;
    const int lane = tid & 31;
    const int wid  = tid >> 5;
    const int g    = lane >> 2;
    const int tig  = lane & 3;
    const int wm   = (wid & 1) * 64;
    const int wn   = (wid >> 1) * 32;

    const uint32_t base = smem_u32(smem);

    // A loads: thread covers 4 rows, float4 at col (tid&7)*4
    const int acol = (tid & 7) * 4;
    const float* arow[4];
    bool aval[4];
#pragma unroll
    for (int v = 0; v < 4; v++) {
        const int r  = v * 32 + (tid >> 3);
        const int gr = m0 + r;
        if (GROUPED) {
            aval[v] = (gr < rows);
            int row = 0;
            if (aval[v]) row = GATHER ? g_perm[segBase + gr] : (segBase + gr);
            arow[v] = Asrc + (size_t)row * K + acol;
        } else {
            aval[v] = true;
            arow[v] = Asrc + (size_t)gr * K + acol;
        }
    }
    // A smem store offset within a stage (uint2 at [r][acol>>1])
    const uint32_t a_st = (((tid >> 3) * TSTRIDE) + (acol >> 1)) * 4;

    // B loads: thread covers col = tid>>1, 8 kpairs starting (tid&1)*8
    const int bcol  = tid >> 1;
    const int bkp   = (tid & 1) * 8;
    const uint32_t* bptrH = BpH + (size_t)(n0 + bcol) * (K / 2) + bkp;
    const uint32_t* bptrL = BpL + (size_t)(n0 + bcol) * (K / 2) + bkp;
    const uint32_t b_st = (bcol * TSTRIDE + bkp) * 4;

    // ldmatrix per-lane addresses (stage-local byte offsets)
    const uint32_t a_off = (((wm + (lane & 15)) * TSTRIDE) + ((lane >> 4) * 4)) * 4;
    const uint32_t b_off = (((wn + ((lane >> 4) & 1) * 8 + (lane & 7)) * TSTRIDE)
                            + (((lane >> 3) & 1) * 4)) * 4;

    float acc[4][4][4];
#pragma unroll
    for (int m = 0; m < 4; m++)
#pragma unroll
        for (int n = 0; n < 4; n++)
#pragma unroll
            for (int i = 0; i < 4; i++) acc[m][n][i] = 0.0f;

    const int KT = K / 32;

    auto issue_B = [&](int kt, int j) {
        const int kpo = kt * 16;
        const uint32_t dB = base + (4 + 2 * j) * TILE_B + b_st;
        CP16(dB,               bptrH + kpo);
        CP16(dB + 16,          bptrH + kpo + 4);
        CP16(dB + TILE_B,      bptrL + kpo);
        CP16(dB + TILE_B + 16, bptrL + kpo + 4);
        asm volatile("cp.async.commit_group;");
    };
    float4 areg[4];
    auto convert_A = [&](int sa) {
        const uint32_t sbase = base + sa * 2 * TILE_B;
#pragma unroll
        for (int v = 0; v < 4; v++) {
            const float hx = bf16_rt(areg[v].x), hy = bf16_rt(areg[v].y);
            const float hz = bf16_rt(areg[v].z), hw = bf16_rt(areg[v].w);
            uint2 hv, lv;
            hv.x = pack_bf16x2(hx, hy);
            hv.y = pack_bf16x2(hz, hw);
            lv.x = pack_bf16x2(areg[v].x - hx, areg[v].y - hy);
            lv.y = pack_bf16x2(areg[v].z - hz, areg[v].w - hw);
            const uint32_t d = sbase + a_st + v * 32 * TSTRIDE * 4;
            asm volatile("st.shared.v2.b32 [%0], {%1,%2};" :: "r"(d), "r"(hv.x), "r"(hv.y));
            asm volatile("st.shared.v2.b32 [%0], {%1,%2};"
                         :: "r"(d + TILE_B), "r"(lv.x), "r"(lv.y));
        }
    };
    auto fetch_A = [&](int kt) {
        const int ko = kt * 32;
#pragma unroll
        for (int v = 0; v < 4; v++) {
            areg[v] = make_float4(0.f, 0.f, 0.f, 0.f);
            if (aval[v]) areg[v] = *reinterpret_cast<const float4*>(arow[v] + ko);
        }
    };

    // ---- preloop ----
    fetch_A(0);
    convert_A(0);
    issue_B(0, 0);
    if (KT > 1) { fetch_A(1); issue_B(1, 1); }

    for (int kt = 0; kt < KT; kt++) {
        const int sA = kt & 1;
        const int sB = kt % 3;
        if (kt + 1 < KT) asm volatile("cp.async.wait_group 1;" ::: "memory");
        else             asm volatile("cp.async.wait_group 0;" ::: "memory");
        __syncthreads();

        if (kt + 2 < KT) issue_B(kt + 2, (kt + 2) % 3);

        const uint32_t aH_addr = base + sA * 2 * TILE_B + a_off;
        const uint32_t aL_addr = aH_addr + TILE_B;
        const uint32_t bH_addr = base + (4 + 2 * sB) * TILE_B + b_off;
        const uint32_t bL_addr = bH_addr + TILE_B;

#pragma unroll
        for (int ks = 0; ks < 2; ks++) {
            const uint32_t ksb = ks * 32;
            uint32_t bH[4][2], bL[4][2];
            ldsm_x4(bH[0][0], bH[0][1], bH[1][0], bH[1][1], bH_addr + ksb);
            ldsm_x4(bH[2][0], bH[2][1], bH[3][0], bH[3][1], bH_addr + ksb + 16 * TSTRIDE * 4);
            ldsm_x4(bL[0][0], bL[0][1], bL[1][0], bL[1][1], bL_addr + ksb);
            ldsm_x4(bL[2][0], bL[2][1], bL[3][0], bL[3][1], bL_addr + ksb + 16 * TSTRIDE * 4);
#pragma unroll
            for (int m = 0; m < 4; m++) {
                const uint32_t mb = m * 16 * TSTRIDE * 4;
                uint32_t aH[4], aL[4];
                ldsm_x4(aH[0], aH[1], aH[2], aH[3], aH_addr + mb + ksb);
                ldsm_x4(aL[0], aL[1], aL[2], aL[3], aL_addr + mb + ksb);
#pragma unroll
                for (int n = 0; n < 4; n++) {
                    mma_bf16(acc[m][n], aH, bH[n]);
                    mma_bf16(acc[m][n], aH, bL[n]);
                    mma_bf16(acc[m][n], aL, bH[n]);
                }
            }
        }

        if (kt + 1 < KT) {
            convert_A((kt + 1) & 1);
            if (kt + 2 < KT) fetch_A(kt + 2);
        }
    }

    // ---- epilogue ----
    if (OUT_ATOMIC) {
        // fused combine: Cout treated as [NSUB][N] accumulator
#pragma unroll
        for (int m = 0; m < 4; m++) {
            const int r0 = wm + m * 16 + g;
            int   tok[2]; float w[2]; bool ok[2];
#pragma unroll
            for (int h = 0; h < 2; h++) {
                const int gr = m0 + r0 + 8 * h;
                ok[h] = gr < rows;
                if (ok[h]) {
                    const int slot = segBase + gr;
                    tok[h] = g_perm[slot];
                    w[h]   = g_wslot[slot];
                } else { tok[h] = 0; w[h] = 0.f; }
            }
#pragma unroll
            for (int n = 0; n < 4; n++) {
                const int col = n0 + wn + n * 8 + 2 * tig;
                const float b0 = bias[col];
                const float b1 = bias[col + 1];
                if (ok[0]) {
                    float* p = Cout + (size_t)tok[0] * N + col;
                    atomicAdd(p,     w[0] * (acc[m][n][0] + b0));
                    atomicAdd(p + 1, w[0] * (acc[m][n][1] + b1));
                }
                if (ok[1]) {
                    float* p = Cout + (size_t)tok[1] * N + col;
                    atomicAdd(p,     w[1] * (acc[m][n][2] + b0));
                    atomicAdd(p + 1, w[1] * (acc[m][n][3] + b1));
                }
            }
        }
    } else {
#pragma unroll
        for (int n = 0; n < 4; n++) {
            const int col = n0 + wn + n * 8 + 2 * tig;
            const float b0 = bias[col];
            const float b1 = bias[col + 1];
#pragma unroll
            for (int m = 0; m < 4; m++) {
                const int r0 = wm + m * 16 + g;
                float v00 = acc[m][n][0] + b0;
                float v01 = acc[m][n][1] + b1;
                float v10 = acc[m][n][2] + b0;
                float v11 = acc[m][n][3] + b1;
                if (DO_GELU) {
                    v00 = gelu_exact(v00); v01 = gelu_exact(v01);
                    v10 = gelu_exact(v10); v11 = gelu_exact(v11);
                }
                if (GROUPED) {
                    if (m0 + r0 < rows) {
                        float* p = Cout + (size_t)(segBase + m0 + r0) * N + col;
                        *reinterpret_cast<float2*>(p) = make_float2(v00, v01);
                    }
                    if (m0 + r0 + 8 < rows) {
                        float* p = Cout + (size_t)(segBase + m0 + r0 + 8) * N + col;
                        *reinterpret_cast<float2*>(p) = make_float2(v10, v11);
                    }
                } else {
                    float* p0 = Cout + (size_t)(m0 + r0) * N + col;
                    float* p1 = Cout + (size_t)(m0 + r0 + 8) * N + col;
                    *reinterpret_cast<float2*>(p0) = make_float2(v00, v01);
                    *reinterpret_cast<float2*>(p1) = make_float2(v10, v11);
                }
            }
        }
    }
}

// ---------------------------------------------------------------------------
// Routing: one warp per sub-token + fused expert histogram (block-aggregated).
// ---------------------------------------------------------------------------
__global__ void routing_kernel(const float* __restrict__ emb)
{
    __shared__ int loc[NE];
    if (threadIdx.x < NE) loc[threadIdx.x] = 0;
    __syncthreads();

    const int warp = (blockIdx.x * blockDim.x + threadIdx.x) >> 5;
    const int lane = threadIdx.x & 31;

    const float* trow = g_h + (size_t)warp * HD;
    const float tv0 = trow[lane];
    const float tv1 = trow[lane + 32];
    const float tv2 = trow[lane + 64];
    const float tv3 = trow[lane + 96];

    float logits[NE];
#pragma unroll
    for (int e = 0; e < NE; e++) {
        float p = tv0 * emb[(lane      ) * NE + e]
                + tv1 * emb[(lane + 32 ) * NE + e]
                + tv2 * emb[(lane + 64 ) * NE + e]
                + tv3 * emb[(lane + 96 ) * NE + e];
#pragma unroll
        for (int s = 16; s > 0; s >>= 1) p += __shfl_xor_sync(0xffffffffu, p, s);
        logits[e] = p;
    }

    float mx = logits[0];
#pragma unroll
    for (int e = 1; e < NE; e++) mx = fmaxf(mx, logits[e]);
    float sum = 0.0f;
#pragma unroll
    for (int e = 0; e < NE; e++) { logits[e] = expf(logits[e] - mx); sum += logits[e]; }
    const float inv = 1.0f / sum;

    int i0 = 0; float v0 = logits[0];
#pragma unroll
    for (int e = 1; e < NE; e++) if (logits[e] > v0) { v0 = logits[e]; i0 = e; }
    int i1 = -1; float v1 = -1.0f;
#pragma unroll
    for (int e = 0; e < NE; e++) if (e != i0 && logits[e] > v1) { v1 = logits[e]; i1 = e; }

    if (lane == 0) {
        g_topi[2 * warp + 0] = i0;
        g_topi[2 * warp + 1] = i1;
        g_topw[2 * warp + 0] = v0 * inv;
        g_topw[2 * warp + 1] = v1 * inv;
        atomicAdd(&loc[i0], 1);
        atomicAdd(&loc[i1], 1);
    }
    __syncthreads();
    if (threadIdx.x < NE && loc[threadIdx.x])
        atomicAdd(&g_counts[threadIdx.x], loc[threadIdx.x]);
}

// ---------------------------------------------------------------------------
// Routing bookkeeping
// ---------------------------------------------------------------------------
__global__ void zero_counts() {
    int i = threadIdx.x;
    if (i < NE) { g_counts[i] = 0; g_cursor[i] = 0; }
}
__global__ void scan_kernel() {
    int s = 0;
    for (int e = 0; e < NE; e++) { g_offsets[e] = s; s += g_counts[e]; }
    g_offsets[NE] = s;
}
__global__ void build_tiles() {
    const int e = threadIdx.x;
    if (e >= NE) return;
    int start = 0;
#pragma unroll
    for (int j = 0; j < NE; j++) {
        int tj = (g_counts[j] + 127) >> 7;
        if (j < e) start += tj;
        if (e == NE - 1 && j == NE - 1) g_ntiles = start + tj;
    }
    const int nt = (g_counts[e] + 127) >> 7;
    for (int t = 0; t < nt; t++)
        g_tilemap[start + t] = make_int2(e, t << 7);
}
__global__ void scatter_kernel() {
    __shared__ int bcnt[NE];
    __shared__ int bbase[NE];
    if (threadIdx.x < NE) bcnt[threadIdx.x] = 0;
    __syncthreads();

    const int i    = blockIdx.x * blockDim.x + threadIdx.x;
    const int lane = threadIdx.x & 31;
    const int e    = g_topi[i];

    unsigned mask    = __match_any_sync(0xffffffffu, e);
    const int leader = __ffs(mask) - 1;
    const int lrank  = __popc(mask & ((1u << lane) - 1));
    int wbase = 0;
    if (lane == leader) wbase = atomicAdd(&bcnt[e], __popc(mask));
    wbase = __shfl_sync(0xffffffffu, wbase, leader);
    __syncthreads();

    if (threadIdx.x < NE)
        bbase[threadIdx.x] = bcnt[threadIdx.x]
            ? atomicAdd(&g_cursor[threadIdx.x], bcnt[threadIdx.x]) : 0;
    __syncthreads();

    const int slot = g_offsets[e] + bbase[e] + wbase + lrank;
    g_perm[slot]  = i >> 1;
    g_wslot[slot] = g_topw[i];
}

// ---------------------------------------------------------------------------
// Launch
// ---------------------------------------------------------------------------
extern "C" void kernel_launch(void* const* d_in, const int* in_sizes, int n_in,
                              void* d_out, int out_size)
{
    (void)in_sizes; (void)n_in; (void)out_size;
    const float* x   = (const float*)d_in[0];
    const float* Wm  = (const float*)d_in[1];
    const float* bm  = (const float*)d_in[2];
    const float* emb = (const float*)d_in[3];
    const float* W1  = (const float*)d_in[4];
    const float* b1  = (const float*)d_in[5];
    const float* W2  = (const float*)d_in[6];
    const float* b2  = (const float*)d_in[7];
    const float* Wo  = (const float*)d_in[8];
    const float* bo  = (const float*)d_in[9];
    float* out = (float*)d_out;

    float *h_p, *comb_p, *hmid_p;
    cudaGetSymbolAddress((void**)&h_p,    g_h);
    cudaGetSymbolAddress((void**)&comb_p, g_comb);
    cudaGetSymbolAddress((void**)&hmid_p, g_hmid);
    uint32_t *WmH, *WmL, *W1H, *W1L, *W2H, *W2L, *WoH, *WoL;
    cudaGetSymbolAddress((void**)&WmH, g_WmH); cudaGetSymbolAddress((void**)&WmL, g_WmL);
    cudaGetSymbolAddress((void**)&W1H, g_W1H); cudaGetSymbolAddress((void**)&W1L, g_W1L);
    cudaGetSymbolAddress((void**)&W2H, g_W2H); cudaGetSymbolAddress((void**)&W2L, g_W2L);
    cudaGetSymbolAddress((void**)&WoH, g_WoH); cudaGetSymbolAddress((void**)&WoL, g_WoL);

    cudaFuncSetAttribute(mma_gemm<false,false,false,false>,
                         cudaFuncAttributeMaxDynamicSharedMemorySize, SMEM_BYTES);
    cudaFuncSetAttribute(mma_gemm<true,true,true,false>,
                         cudaFuncAttributeMaxDynamicSharedMemorySize, SMEM_BYTES);
    cudaFuncSetAttribute(mma_gemm<true,false,false,true>,
                         cudaFuncAttributeMaxDynamicSharedMemorySize, SMEM_BYTES);

    // 0) prepack weights + zero combine accumulator + zero counts
    zero_comb<<<(NTOK * DIM / 4) / 256, 256>>>();
    zero_counts<<<1, 32>>>();
    prepack_kernel<<<dim3(DIM/32, DIM/64, 1),  256>>>(Wm, WmH, WmL, DIM, DIM);
    prepack_kernel<<<dim3(II/32,  HD/64,  NE), 256>>>(W1, W1H, W1L, HD, II);
    prepack_kernel<<<dim3(HD/32,  II/64,  NE), 256>>>(W2, W2H, W2L, II, HD);
    prepack_kernel<<<dim3(DIM/32, DIM/64, 1),  256>>>(Wo, WoH, WoL, DIM, DIM);

    // 1) h = x @ Wm + bm
    mma_gemm<false,false,false,false><<<dim3(DIM/128, NTOK/128), 256, SMEM_BYTES>>>(
        x, WmH, WmL, bm, h_p, NTOK, DIM, DIM);

    // 2) routing (+ fused histogram)
    routing_kernel<<<NSUB / 16, 512>>>(emb);

    // 3) expert bookkeeping + tile worklist
    scan_kernel<<<1, 1>>>();
    build_tiles<<<1, NE>>>();
    scatter_kernel<<<NPAIR / 256, 256>>>();

    // 4) hmid = gelu(t @ W1[e] + b1[e])  — TRANSPOSED grid: n fastest,
    //    so the 4 CTAs sharing a tile's gathered A rows are launch-adjacent.
    mma_gemm<true,true,true,false><<<dim3(II/128, MAXTILES), 256, SMEM_BYTES>>>(
        h_p, W1H, W1L, b1, hmid_p, 0, II, HD);

    // 5) eo = hmid @ W2[e] + b2[e], fused w-scaled atomic combine into comb
    mma_gemm<true,false,false,true><<<dim3(HD/128, MAXTILES), 256, SMEM_BYTES>>>(
        hmid_p, W2H, W2L, b2, comb_p, 0, HD, II);

    // 6) out = comb @ Wo + bo
    mma_gemm<false,false,false,false><<<dim3(DIM/128, NTOK/128), 256, SMEM_BYTES>>>(
        comb_p, WoH, WoL, bo, out, NTOK, DIM, DIM);
}

// round 17
// speedup vs baseline: 1.2918x; 1.0026x over previous
#include <cuda_runtime.h>
#include <cuda_bf16.h>
#include <math.h>
#include <stdint.h>

// ---------------------------------------------------------------------------
// Problem constants
// ---------------------------------------------------------------------------
#define BSZ   4
#define LEN   2048
#define DIM   1024
#define NH    8
#define NE    16
#define TOPK  2
#define HD    128
#define II    512
#define NTOK  (BSZ*LEN)    // 8192
#define NSUB  (NTOK*NH)    // 65536
#define NPAIR (NSUB*TOPK)  // 131072
#define MAXTILES (NPAIR/128 + NE)   // 1040

// ---------------------------------------------------------------------------
// Device scratch
// ---------------------------------------------------------------------------
__device__ float g_h   [(size_t)NTOK * DIM];
__device__ float g_comb[(size_t)NTOK * DIM];
__device__ float g_hmid[(size_t)NPAIR * II];
__device__ int   g_topi[NPAIR];
__device__ float g_topw[NPAIR];
__device__ int   g_perm[NPAIR];
__device__ float g_wslot[NPAIR];
__device__ int   g_counts[NE];
__device__ int   g_cursor[NE];
__device__ int   g_offsets[NE + 1];
__device__ int2  g_tilemap[MAXTILES];
__device__ int   g_ntiles;

// Prepacked weights: hi/lo bf16x2 (packed along k), transposed to [N][K/2]
__device__ uint32_t g_WmH[(size_t)DIM * DIM / 2];
__device__ uint32_t g_WmL[(size_t)DIM * DIM / 2];
__device__ uint32_t g_W1H[(size_t)NE * II * HD / 2];
__device__ uint32_t g_W1L[(size_t)NE * II * HD / 2];
__device__ uint32_t g_W2H[(size_t)NE * HD * II / 2];
__device__ uint32_t g_W2L[(size_t)NE * HD * II / 2];
__device__ uint32_t g_WoH[(size_t)DIM * DIM / 2];
__device__ uint32_t g_WoL[(size_t)DIM * DIM / 2];

__device__ __forceinline__ float gelu_exact(float x) {
    return 0.5f * x * (1.0f + erff(x * 0.70710678118654752440f));
}
__device__ __forceinline__ uint32_t pack_bf16x2(float e0, float e1) {
    uint32_t r;
    asm("cvt.rn.bf16x2.f32 %0, %1, %2;" : "=r"(r) : "f"(e1), "f"(e0));
    return r;
}
__device__ __forceinline__ float bf16_rt(float x) {
    return __bfloat162float(__float2bfloat16(x));
}
__device__ __forceinline__ void mma_bf16(float* d, const uint32_t* a, const uint32_t* b) {
    asm volatile(
        "mma.sync.aligned.m16n8k16.row.col.f32.bf16.bf16.f32 "
        "{%0,%1,%2,%3}, {%4,%5,%6,%7}, {%8,%9}, {%0,%1,%2,%3};\n"
        : "+f"(d[0]), "+f"(d[1]), "+f"(d[2]), "+f"(d[3])
        : "r"(a[0]), "r"(a[1]), "r"(a[2]), "r"(a[3]), "r"(b[0]), "r"(b[1]));
}
__device__ __forceinline__ void ldsm_x4(uint32_t& r0, uint32_t& r1,
                                        uint32_t& r2, uint32_t& r3, uint32_t addr) {
    asm volatile("ldmatrix.sync.aligned.m8n8.x4.shared.b16 {%0,%1,%2,%3}, [%4];"
                 : "=r"(r0), "=r"(r1), "=r"(r2), "=r"(r3) : "r"(addr));
}
__device__ __forceinline__ uint32_t smem_u32(const void* p) {
    return (uint32_t)__cvta_generic_to_shared(p);
}
__device__ __forceinline__ void red_add_v2(float* p, float v0, float v1) {
    asm volatile("red.global.add.v2.f32 [%0], {%1, %2};"
                 :: "l"(p), "f"(v0), "f"(v1) : "memory");
}

#define CP16(dst, src) \
    asm volatile("cp.async.cg.shared.global [%0], [%1], 16;" :: "r"(dst), "l"(src))

// ---------------------------------------------------------------------------
// Weight prepack: B[K][N] (row-major, per expert) -> hi/lo [N][K/2] uint32
// ---------------------------------------------------------------------------
__global__ void prepack_kernel(const float* __restrict__ B,
                               uint32_t* __restrict__ Hi, uint32_t* __restrict__ Lo,
                               int K, int N)
{
    const int e = blockIdx.z;
    B  += (size_t)e * K * N;
    Hi += (size_t)e * N * (K / 2);
    Lo += (size_t)e * N * (K / 2);

    __shared__ float tile[64][33];
    const int tid = threadIdx.x;
    const int k0 = blockIdx.y * 64;
    const int n0 = blockIdx.x * 32;

#pragma unroll
    for (int i = 0; i < 8; i++) {
        const int row = i * 8 + (tid >> 5);
        const int col = tid & 31;
        tile[row][col] = B[(size_t)(k0 + row) * N + n0 + col];
    }
    __syncthreads();

#pragma unroll
    for (int j = 0; j < 4; j++) {
        const int nl = (tid >> 5) * 4 + j;
        const int kp = tid & 31;
        const float x0 = tile[2 * kp][nl];
        const float x1 = tile[2 * kp + 1][nl];
        const float h0 = bf16_rt(x0), h1 = bf16_rt(x1);
        const size_t o = (size_t)(n0 + nl) * (K / 2) + k0 / 2 + kp;
        Hi[o] = pack_bf16x2(h0, h1);
        Lo[o] = pack_bf16x2(x0 - h0, x1 - h1);
    }
}

// ---------------------------------------------------------------------------
// Zero the combine accumulator (float4 stream).
// ---------------------------------------------------------------------------
__global__ void zero_comb() {
    int i = blockIdx.x * blockDim.x + threadIdx.x;
    reinterpret_cast<float4*>(g_comb)[i] = make_float4(0.f, 0.f, 0.f, 0.f);
}

// ---------------------------------------------------------------------------
// bf16-split tensor GEMM (R16 engine).
// GROUPED grid is TRANSPOSED: blockIdx.x = n-tile (fastest), blockIdx.y =
// flat worklist tile — CTAs sharing gathered A rows are launch-adjacent.
// OUT_ATOMIC: epilogue scales by g_wslot[slot] and accumulates into
// g_comb[g_perm[slot]*N + col] via red.global.add.v2.f32 (fused combine).
// ---------------------------------------------------------------------------
#define TSTRIDE 20
#define TILE_B  (128 * TSTRIDE * 4)       // 10240 bytes
#define SMEM_BYTES (10 * TILE_B)          // 102400

template<bool GROUPED, bool GATHER, bool DO_GELU, bool OUT_ATOMIC>
__global__ __launch_bounds__(256, 2)
void mma_gemm(const float* __restrict__ Asrc,
              const uint32_t* __restrict__ BpH, const uint32_t* __restrict__ BpL,
              const float* __restrict__ biasAll, float* __restrict__ Cout,
              int M, int N, int K)
{
    extern __shared__ __align__(16) uint32_t smem[];

    int rows = M, segBase = 0, m0, n0;
    const float* bias;
    if (GROUPED) {
        if ((int)blockIdx.y >= g_ntiles) return;
        const int2 tm = g_tilemap[blockIdx.y];
        const int e = tm.x;
        m0      = tm.y;
        rows    = g_counts[e];
        segBase = g_offsets[e];
        n0      = blockIdx.x * 128;
        BpH    += (size_t)e * N * (K / 2);
        BpL    += (size_t)e * N * (K / 2);
        bias    = biasAll + (size_t)e * N;
    } else {
        m0   = blockIdx.y * 128;
        n0   = blockIdx.x * 128;
        bias = biasAll;
    }

    const int tid  = threadIdx.x;
    const int lane = tid & 31;
    const int wid  = tid >> 5;
    const int g    = lane >> 2;
    const int tig  = lane & 3;
    const int wm   = (wid & 1) * 64;
    const int wn   = (wid >> 1) * 32;

    const uint32_t base = smem_u32(smem);

    // A loads: thread covers 4 rows, float4 at col (tid&7)*4
    const int acol = (tid & 7) * 4;
    const float* arow[4];
    bool aval[4];
#pragma unroll
    for (int v = 0; v < 4; v++) {
        const int r  = v * 32 + (tid >> 3);
        const int gr = m0 + r;
        if (GROUPED) {
            aval[v] = (gr < rows);
            int row = 0;
            if (aval[v]) row = GATHER ? g_perm[segBase + gr] : (segBase + gr);
            arow[v] = Asrc + (size_t)row * K + acol;
        } else {
            aval[v] = true;
            arow[v] = Asrc + (size_t)gr * K + acol;
        }
    }
    // A smem store offset within a stage (uint2 at [r][acol>>1])
    const uint32_t a_st = (((tid >> 3) * TSTRIDE) + (acol >> 1)) * 4;

    // B loads: thread covers col = tid>>1, 8 kpairs starting (tid&1)*8
    const int bcol  = tid >> 1;
    const int bkp   = (tid & 1) * 8;
    const uint32_t* bptrH = BpH + (size_t)(n0 + bcol) * (K / 2) + bkp;
    const uint32_t* bptrL = BpL + (size_t)(n0 + bcol) * (K / 2) + bkp;
    const uint32_t b_st = (bcol * TSTRIDE + bkp) * 4;

    // ldmatrix per-lane addresses (stage-local byte offsets)
    const uint32_t a_off = (((wm + (lane & 15)) * TSTRIDE) + ((lane >> 4) * 4)) * 4;
    const uint32_t b_off = (((wn + ((lane >> 4) & 1) * 8 + (lane & 7)) * TSTRIDE)
                            + (((lane >> 3) & 1) * 4)) * 4;

    float acc[4][4][4];
#pragma unroll
    for (int m = 0; m < 4; m++)
#pragma unroll
        for (int n = 0; n < 4; n++)
#pragma unroll
            for (int i = 0; i < 4; i++) acc[m][n][i] = 0.0f;

    const int KT = K / 32;

    auto issue_B = [&](int kt, int j) {
        const int kpo = kt * 16;
        const uint32_t dB = base + (4 + 2 * j) * TILE_B + b_st;
        CP16(dB,               bptrH + kpo);
        CP16(dB + 16,          bptrH + kpo + 4);
        CP16(dB + TILE_B,      bptrL + kpo);
        CP16(dB + TILE_B + 16, bptrL + kpo + 4);
        asm volatile("cp.async.commit_group;");
    };
    float4 areg[4];
    auto convert_A = [&](int sa) {
        const uint32_t sbase = base + sa * 2 * TILE_B;
#pragma unroll
        for (int v = 0; v < 4; v++) {
            const float hx = bf16_rt(areg[v].x), hy = bf16_rt(areg[v].y);
            const float hz = bf16_rt(areg[v].z), hw = bf16_rt(areg[v].w);
            uint2 hv, lv;
            hv.x = pack_bf16x2(hx, hy);
            hv.y = pack_bf16x2(hz, hw);
            lv.x = pack_bf16x2(areg[v].x - hx, areg[v].y - hy);
            lv.y = pack_bf16x2(areg[v].z - hz, areg[v].w - hw);
            const uint32_t d = sbase + a_st + v * 32 * TSTRIDE * 4;
            asm volatile("st.shared.v2.b32 [%0], {%1,%2};" :: "r"(d), "r"(hv.x), "r"(hv.y));
            asm volatile("st.shared.v2.b32 [%0], {%1,%2};"
                         :: "r"(d + TILE_B), "r"(lv.x), "r"(lv.y));
        }
    };
    auto fetch_A = [&](int kt) {
        const int ko = kt * 32;
#pragma unroll
        for (int v = 0; v < 4; v++) {
            areg[v] = make_float4(0.f, 0.f, 0.f, 0.f);
            if (aval[v]) areg[v] = *reinterpret_cast<const float4*>(arow[v] + ko);
        }
    };

    // ---- preloop ----
    fetch_A(0);
    convert_A(0);
    issue_B(0, 0);
    if (KT > 1) { fetch_A(1); issue_B(1, 1); }

    for (int kt = 0; kt < KT; kt++) {
        const int sA = kt & 1;
        const int sB = kt % 3;
        if (kt + 1 < KT) asm volatile("cp.async.wait_group 1;" ::: "memory");
        else             asm volatile("cp.async.wait_group 0;" ::: "memory");
        __syncthreads();

        if (kt + 2 < KT) issue_B(kt + 2, (kt + 2) % 3);

        const uint32_t aH_addr = base + sA * 2 * TILE_B + a_off;
        const uint32_t aL_addr = aH_addr + TILE_B;
        const uint32_t bH_addr = base + (4 + 2 * sB) * TILE_B + b_off;
        const uint32_t bL_addr = bH_addr + TILE_B;

#pragma unroll
        for (int ks = 0; ks < 2; ks++) {
            const uint32_t ksb = ks * 32;
            uint32_t bH[4][2], bL[4][2];
            ldsm_x4(bH[0][0], bH[0][1], bH[1][0], bH[1][1], bH_addr + ksb);
            ldsm_x4(bH[2][0], bH[2][1], bH[3][0], bH[3][1], bH_addr + ksb + 16 * TSTRIDE * 4);
            ldsm_x4(bL[0][0], bL[0][1], bL[1][0], bL[1][1], bL_addr + ksb);
            ldsm_x4(bL[2][0], bL[2][1], bL[3][0], bL[3][1], bL_addr + ksb + 16 * TSTRIDE * 4);
#pragma unroll
            for (int m = 0; m < 4; m++) {
                const uint32_t mb = m * 16 * TSTRIDE * 4;
                uint32_t aH[4], aL[4];
                ldsm_x4(aH[0], aH[1], aH[2], aH[3], aH_addr + mb + ksb);
                ldsm_x4(aL[0], aL[1], aL[2], aL[3], aL_addr + mb + ksb);
#pragma unroll
                for (int n = 0; n < 4; n++) {
                    mma_bf16(acc[m][n], aH, bH[n]);
                    mma_bf16(acc[m][n], aH, bL[n]);
                    mma_bf16(acc[m][n], aL, bH[n]);
                }
            }
        }

        if (kt + 1 < KT) {
            convert_A((kt + 1) & 1);
            if (kt + 2 < KT) fetch_A(kt + 2);
        }
    }

    // ---- epilogue ----
    if (OUT_ATOMIC) {
        // fused combine: Cout treated as [NSUB][N] accumulator
#pragma unroll
        for (int m = 0; m < 4; m++) {
            const int r0 = wm + m * 16 + g;
            int   tok[2]; float w[2]; bool ok[2];
#pragma unroll
            for (int h = 0; h < 2; h++) {
                const int gr = m0 + r0 + 8 * h;
                ok[h] = gr < rows;
                if (ok[h]) {
                    const int slot = segBase + gr;
                    tok[h] = g_perm[slot];
                    w[h]   = g_wslot[slot];
                } else { tok[h] = 0; w[h] = 0.f; }
            }
#pragma unroll
            for (int n = 0; n < 4; n++) {
                const int col = n0 + wn + n * 8 + 2 * tig;
                const float b0 = bias[col];
                const float b1 = bias[col + 1];
                if (ok[0]) {
                    float* p = Cout + (size_t)tok[0] * N + col;
                    red_add_v2(p, w[0] * (acc[m][n][0] + b0),
                                  w[0] * (acc[m][n][1] + b1));
                }
                if (ok[1]) {
                    float* p = Cout + (size_t)tok[1] * N + col;
                    red_add_v2(p, w[1] * (acc[m][n][2] + b0),
                                  w[1] * (acc[m][n][3] + b1));
                }
            }
        }
    } else {
#pragma unroll
        for (int n = 0; n < 4; n++) {
            const int col = n0 + wn + n * 8 + 2 * tig;
            const float b0 = bias[col];
            const float b1 = bias[col + 1];
#pragma unroll
            for (int m = 0; m < 4; m++) {
                const int r0 = wm + m * 16 + g;
                float v00 = acc[m][n][0] + b0;
                float v01 = acc[m][n][1] + b1;
                float v10 = acc[m][n][2] + b0;
                float v11 = acc[m][n][3] + b1;
                if (DO_GELU) {
                    v00 = gelu_exact(v00); v01 = gelu_exact(v01);
                    v10 = gelu_exact(v10); v11 = gelu_exact(v11);
                }
                if (GROUPED) {
                    if (m0 + r0 < rows) {
                        float* p = Cout + (size_t)(segBase + m0 + r0) * N + col;
                        *reinterpret_cast<float2*>(p) = make_float2(v00, v01);
                    }
                    if (m0 + r0 + 8 < rows) {
                        float* p = Cout + (size_t)(segBase + m0 + r0 + 8) * N + col;
                        *reinterpret_cast<float2*>(p) = make_float2(v10, v11);
                    }
                } else {
                    float* p0 = Cout + (size_t)(m0 + r0) * N + col;
                    float* p1 = Cout + (size_t)(m0 + r0 + 8) * N + col;
                    *reinterpret_cast<float2*>(p0) = make_float2(v00, v01);
                    *reinterpret_cast<float2*>(p1) = make_float2(v10, v11);
                }
            }
        }
    }
}

// ---------------------------------------------------------------------------
// Routing: one warp per sub-token + fused expert histogram (block-aggregated).
// ---------------------------------------------------------------------------
__global__ void routing_kernel(const float* __restrict__ emb)
{
    __shared__ int loc[NE];
    if (threadIdx.x < NE) loc[threadIdx.x] = 0;
    __syncthreads();

    const int warp = (blockIdx.x * blockDim.x + threadIdx.x) >> 5;
    const int lane = threadIdx.x & 31;

    const float* trow = g_h + (size_t)warp * HD;
    const float tv0 = trow[lane];
    const float tv1 = trow[lane + 32];
    const float tv2 = trow[lane + 64];
    const float tv3 = trow[lane + 96];

    float logits[NE];
#pragma unroll
    for (int e = 0; e < NE; e++) {
        float p = tv0 * emb[(lane      ) * NE + e]
                + tv1 * emb[(lane + 32 ) * NE + e]
                + tv2 * emb[(lane + 64 ) * NE + e]
                + tv3 * emb[(lane + 96 ) * NE + e];
#pragma unroll
        for (int s = 16; s > 0; s >>= 1) p += __shfl_xor_sync(0xffffffffu, p, s);
        logits[e] = p;
    }

    float mx = logits[0];
#pragma unroll
    for (int e = 1; e < NE; e++) mx = fmaxf(mx, logits[e]);
    float sum = 0.0f;
#pragma unroll
    for (int e = 0; e < NE; e++) { logits[e] = expf(logits[e] - mx); sum += logits[e]; }
    const float inv = 1.0f / sum;

    int i0 = 0; float v0 = logits[0];
#pragma unroll
    for (int e = 1; e < NE; e++) if (logits[e] > v0) { v0 = logits[e]; i0 = e; }
    int i1 = -1; float v1 = -1.0f;
#pragma unroll
    for (int e = 0; e < NE; e++) if (e != i0 && logits[e] > v1) { v1 = logits[e]; i1 = e; }

    if (lane == 0) {
        g_topi[2 * warp + 0] = i0;
        g_topi[2 * warp + 1] = i1;
        g_topw[2 * warp + 0] = v0 * inv;
        g_topw[2 * warp + 1] = v1 * inv;
        atomicAdd(&loc[i0], 1);
        atomicAdd(&loc[i1], 1);
    }
    __syncthreads();
    if (threadIdx.x < NE && loc[threadIdx.x])
        atomicAdd(&g_counts[threadIdx.x], loc[threadIdx.x]);
}

// ---------------------------------------------------------------------------
// Routing bookkeeping
// ---------------------------------------------------------------------------
__global__ void zero_counts() {
    int i = threadIdx.x;
    if (i < NE) { g_counts[i] = 0; g_cursor[i] = 0; }
}
__global__ void scan_kernel() {
    int s = 0;
    for (int e = 0; e < NE; e++) { g_offsets[e] = s; s += g_counts[e]; }
    g_offsets[NE] = s;
}
__global__ void build_tiles() {
    const int e = threadIdx.x;
    if (e >= NE) return;
    int start = 0;
#pragma unroll
    for (int j = 0; j < NE; j++) {
        int tj = (g_counts[j] + 127) >> 7;
        if (j < e) start += tj;
        if (e == NE - 1 && j == NE - 1) g_ntiles = start + tj;
    }
    const int nt = (g_counts[e] + 127) >> 7;
    for (int t = 0; t < nt; t++)
        g_tilemap[start + t] = make_int2(e, t << 7);
}
__global__ void scatter_kernel() {
    __shared__ int bcnt[NE];
    __shared__ int bbase[NE];
    if (threadIdx.x < NE) bcnt[threadIdx.x] = 0;
    __syncthreads();

    const int i    = blockIdx.x * blockDim.x + threadIdx.x;
    const int lane = threadIdx.x & 31;
    const int e    = g_topi[i];

    unsigned mask    = __match_any_sync(0xffffffffu, e);
    const int leader = __ffs(mask) - 1;
    const int lrank  = __popc(mask & ((1u << lane) - 1));
    int wbase = 0;
    if (lane == leader) wbase = atomicAdd(&bcnt[e], __popc(mask));
    wbase = __shfl_sync(0xffffffffu, wbase, leader);
    __syncthreads();

    if (threadIdx.x < NE)
        bbase[threadIdx.x] = bcnt[threadIdx.x]
            ? atomicAdd(&g_cursor[threadIdx.x], bcnt[threadIdx.x]) : 0;
    __syncthreads();

    const int slot = g_offsets[e] + bbase[e] + wbase + lrank;
    g_perm[slot]  = i >> 1;
    g_wslot[slot] = g_topw[i];
}

// ---------------------------------------------------------------------------
// Launch
// ---------------------------------------------------------------------------
extern "C" void kernel_launch(void* const* d_in, const int* in_sizes, int n_in,
                              void* d_out, int out_size)
{
    (void)in_sizes; (void)n_in; (void)out_size;
    const float* x   = (const float*)d_in[0];
    const float* Wm  = (const float*)d_in[1];
    const float* bm  = (const float*)d_in[2];
    const float* emb = (const float*)d_in[3];
    const float* W1  = (const float*)d_in[4];
    const float* b1  = (const float*)d_in[5];
    const float* W2  = (const float*)d_in[6];
    const float* b2  = (const float*)d_in[7];
    const float* Wo  = (const float*)d_in[8];
    const float* bo  = (const float*)d_in[9];
    float* out = (float*)d_out;

    float *h_p, *comb_p, *hmid_p;
    cudaGetSymbolAddress((void**)&h_p,    g_h);
    cudaGetSymbolAddress((void**)&comb_p, g_comb);
    cudaGetSymbolAddress((void**)&hmid_p, g_hmid);
    uint32_t *WmH, *WmL, *W1H, *W1L, *W2H, *W2L, *WoH, *WoL;
    cudaGetSymbolAddress((void**)&WmH, g_WmH); cudaGetSymbolAddress((void**)&WmL, g_WmL);
    cudaGetSymbolAddress((void**)&W1H, g_W1H); cudaGetSymbolAddress((void**)&W1L, g_W1L);
    cudaGetSymbolAddress((void**)&W2H, g_W2H); cudaGetSymbolAddress((void**)&W2L, g_W2L);
    cudaGetSymbolAddress((void**)&WoH, g_WoH); cudaGetSymbolAddress((void**)&WoL, g_WoL);

    cudaFuncSetAttribute(mma_gemm<false,false,false,false>,
                         cudaFuncAttributeMaxDynamicSharedMemorySize, SMEM_BYTES);
    cudaFuncSetAttribute(mma_gemm<true,true,true,false>,
                         cudaFuncAttributeMaxDynamicSharedMemorySize, SMEM_BYTES);
    cudaFuncSetAttribute(mma_gemm<true,false,false,true>,
                         cudaFuncAttributeMaxDynamicSharedMemorySize, SMEM_BYTES);

    // 0) prepack weights + zero combine accumulator + zero counts
    zero_comb<<<(NTOK * DIM / 4) / 256, 256>>>();
    zero_counts<<<1, 32>>>();
    prepack_kernel<<<dim3(DIM/32, DIM/64, 1),  256>>>(Wm, WmH, WmL, DIM, DIM);
    prepack_kernel<<<dim3(II/32,  HD/64,  NE), 256>>>(W1, W1H, W1L, HD, II);
    prepack_kernel<<<dim3(HD/32,  II/64,  NE), 256>>>(W2, W2H, W2L, II, HD);
    prepack_kernel<<<dim3(DIM/32, DIM/64, 1),  256>>>(Wo, WoH, WoL, DIM, DIM);

    // 1) h = x @ Wm + bm
    mma_gemm<false,false,false,false><<<dim3(DIM/128, NTOK/128), 256, SMEM_BYTES>>>(
        x, WmH, WmL, bm, h_p, NTOK, DIM, DIM);

    // 2) routing (+ fused histogram)
    routing_kernel<<<NSUB / 16, 512>>>(emb);

    // 3) expert bookkeeping + tile worklist
    scan_kernel<<<1, 1>>>();
    build_tiles<<<1, NE>>>();
    scatter_kernel<<<NPAIR / 256, 256>>>();

    // 4) hmid = gelu(t @ W1[e] + b1[e])  — transposed grid (n fastest)
    mma_gemm<true,true,true,false><<<dim3(II/128, MAXTILES), 256, SMEM_BYTES>>>(
        h_p, W1H, W1L, b1, hmid_p, 0, II, HD);

    // 5) eo = hmid @ W2[e] + b2[e], fused w-scaled vectorized-red combine
    mma_gemm<true,false,false,true><<<dim3(HD/128, MAXTILES), 256, SMEM_BYTES>>>(
        hmid_p, W2H, W2L, b2, comb_p, 0, HD, II);

    // 6) out = comb @ Wo + bo
    mma_gemm<false,false,false,false><<<dim3(DIM/128, NTOK/128), 256, SMEM_BYTES>>>(
        comb_p, WoH, WoL, bo, out, NTOK, DIM, DIM);
}